// round 1
// baseline (speedup 1.0000x reference)
#include <cuda_runtime.h>
#include <math.h>

// Problem constants
#define BSZ   8
#define NSEQ  4096
#define DMODEL 1024
#define EPSC  1e-5f

// ---------------------------------------------------------------------------
// Scratch (device globals: the sanctioned alloc-free workaround)
// ---------------------------------------------------------------------------
#define XELEMS (8u * 4096u * 1024u)   // 33554432
__device__ float g_qr[XELEMS];        // later overwritten with q = relu(qr)*relu(qi)
__device__ float g_qi[XELEMS];
__device__ float g_k [XELEMS];
__device__ float g_v [XELEMS];
__device__ float g_kv[8u * 1024u * 1024u];
__device__ float g_sk[8u * 1024u];
__device__ float g_sv[8u * 1024u];

// ---------------------------------------------------------------------------
// Tiled SGEMM: 128x128 block tile, BK=8, 256 threads, 8x8 per thread.
// Two layout variants:
//   sgemm_nn: A is [M,K] row-major, B is [K,N] row-major
//   sgemm_tn: A is [K,M] row-major (i.e. logical A^T), B is [K,N] row-major
// MODE 0: C = acc
// MODE 1: C = relu(acc * sk[z*M + row] * sv[z*N + col])
// Batched over blockIdx.z via byte-element strides.
// All dims are exact multiples of the tiles (M,N,K in {1024,4096,32768}).
// ---------------------------------------------------------------------------
#define BM 128
#define BN 128
#define BK 8
#define TM 8
#define TN 8

template <int MODE>
__global__ __launch_bounds__(256)
void sgemm_nn(const float* __restrict__ Ab, const float* __restrict__ Bb,
              float* __restrict__ Cb,
              int M, int N, int K,
              long long strideA, long long strideB, long long strideC,
              const float* __restrict__ aux1, const float* __restrict__ aux2)
{
    const float* A = Ab + (long long)blockIdx.z * strideA;
    const float* B = Bb + (long long)blockIdx.z * strideB;
    float*       C = Cb + (long long)blockIdx.z * strideC;

    __shared__ float As[BK][BM];
    __shared__ float Bs[BK][BN];

    const int tid  = threadIdx.x;
    const int brow = blockIdx.y * BM;
    const int bcol = blockIdx.x * BN;

    // A tile: BM x BK, one float4 per thread (128 rows * 2 float4 cols)
    const int aRow = tid >> 1;          // 0..127
    const int aCol = (tid & 1) * 4;     // 0 or 4
    // B tile: BK x BN, one float4 per thread (8 rows * 32 float4 cols)
    const int bRow = tid >> 5;          // 0..7
    const int bCol = (tid & 31) * 4;    // 0..124

    const int tRow = (tid >> 4) * TM;   // 0..120
    const int tCol = (tid & 15) * TN;   // 0..120

    float acc[TM][TN];
#pragma unroll
    for (int i = 0; i < TM; ++i)
#pragma unroll
        for (int j = 0; j < TN; ++j) acc[i][j] = 0.f;

    const float* Aptr = A + (long long)(brow + aRow) * K + aCol;
    const float* Bptr = B + (long long)bRow * N + bcol + bCol;

    for (int k0 = 0; k0 < K; k0 += BK) {
        float4 av = *reinterpret_cast<const float4*>(Aptr);
        float4 bv = *reinterpret_cast<const float4*>(Bptr);
        As[aCol + 0][aRow] = av.x;
        As[aCol + 1][aRow] = av.y;
        As[aCol + 2][aRow] = av.z;
        As[aCol + 3][aRow] = av.w;
        *reinterpret_cast<float4*>(&Bs[bRow][bCol]) = bv;
        __syncthreads();

#pragma unroll
        for (int k = 0; k < BK; ++k) {
            float4 m0 = *reinterpret_cast<const float4*>(&As[k][tRow]);
            float4 m1 = *reinterpret_cast<const float4*>(&As[k][tRow + 4]);
            float4 n0 = *reinterpret_cast<const float4*>(&Bs[k][tCol]);
            float4 n1 = *reinterpret_cast<const float4*>(&Bs[k][tCol + 4]);
            float rm[TM] = {m0.x, m0.y, m0.z, m0.w, m1.x, m1.y, m1.z, m1.w};
            float rn[TN] = {n0.x, n0.y, n0.z, n0.w, n1.x, n1.y, n1.z, n1.w};
#pragma unroll
            for (int i = 0; i < TM; ++i)
#pragma unroll
                for (int j = 0; j < TN; ++j)
                    acc[i][j] += rm[i] * rn[j];
        }
        __syncthreads();
        Aptr += BK;
        Bptr += (long long)BK * N;
    }

#pragma unroll
    for (int i = 0; i < TM; ++i) {
        const int row = brow + tRow + i;
#pragma unroll
        for (int j = 0; j < TN; j += 4) {
            float4 v;
            if (MODE == 1) {
                const float skv = aux1[(long long)blockIdx.z * M + row];
                const int col = bcol + tCol + j;
                v.x = fmaxf(acc[i][j + 0] * skv * aux2[(long long)blockIdx.z * N + col + 0], 0.f);
                v.y = fmaxf(acc[i][j + 1] * skv * aux2[(long long)blockIdx.z * N + col + 1], 0.f);
                v.z = fmaxf(acc[i][j + 2] * skv * aux2[(long long)blockIdx.z * N + col + 2], 0.f);
                v.w = fmaxf(acc[i][j + 3] * skv * aux2[(long long)blockIdx.z * N + col + 3], 0.f);
            } else {
                v.x = acc[i][j + 0]; v.y = acc[i][j + 1];
                v.z = acc[i][j + 2]; v.w = acc[i][j + 3];
            }
            *reinterpret_cast<float4*>(&C[(long long)row * N + bcol + tCol + j]) = v;
        }
    }
}

template <int MODE>
__global__ __launch_bounds__(256)
void sgemm_tn(const float* __restrict__ Ab, const float* __restrict__ Bb,
              float* __restrict__ Cb,
              int M, int N, int K,
              long long strideA, long long strideB, long long strideC,
              const float* __restrict__ aux1, const float* __restrict__ aux2)
{
    const float* A = Ab + (long long)blockIdx.z * strideA;   // [K, M] row-major
    const float* B = Bb + (long long)blockIdx.z * strideB;   // [K, N] row-major
    float*       C = Cb + (long long)blockIdx.z * strideC;

    __shared__ float As[BK][BM];
    __shared__ float Bs[BK][BN];

    const int tid  = threadIdx.x;
    const int brow = blockIdx.y * BM;
    const int bcol = blockIdx.x * BN;

    // Both tiles are [BK][128]: 8 rows * 32 float4 cols, no transpose needed
    const int lRow = tid >> 5;          // 0..7
    const int lCol = (tid & 31) * 4;    // 0..124

    const int tRow = (tid >> 4) * TM;
    const int tCol = (tid & 15) * TN;

    float acc[TM][TN];
#pragma unroll
    for (int i = 0; i < TM; ++i)
#pragma unroll
        for (int j = 0; j < TN; ++j) acc[i][j] = 0.f;

    const float* Aptr = A + (long long)lRow * M + brow + lCol;
    const float* Bptr = B + (long long)lRow * N + bcol + lCol;

    for (int k0 = 0; k0 < K; k0 += BK) {
        float4 av = *reinterpret_cast<const float4*>(Aptr);
        float4 bv = *reinterpret_cast<const float4*>(Bptr);
        *reinterpret_cast<float4*>(&As[lRow][lCol]) = av;
        *reinterpret_cast<float4*>(&Bs[lRow][lCol]) = bv;
        __syncthreads();

#pragma unroll
        for (int k = 0; k < BK; ++k) {
            float4 m0 = *reinterpret_cast<const float4*>(&As[k][tRow]);
            float4 m1 = *reinterpret_cast<const float4*>(&As[k][tRow + 4]);
            float4 n0 = *reinterpret_cast<const float4*>(&Bs[k][tCol]);
            float4 n1 = *reinterpret_cast<const float4*>(&Bs[k][tCol + 4]);
            float rm[TM] = {m0.x, m0.y, m0.z, m0.w, m1.x, m1.y, m1.z, m1.w};
            float rn[TN] = {n0.x, n0.y, n0.z, n0.w, n1.x, n1.y, n1.z, n1.w};
#pragma unroll
            for (int i = 0; i < TM; ++i)
#pragma unroll
                for (int j = 0; j < TN; ++j)
                    acc[i][j] += rm[i] * rn[j];
        }
        __syncthreads();
        Aptr += (long long)BK * M;
        Bptr += (long long)BK * N;
    }

#pragma unroll
    for (int i = 0; i < TM; ++i) {
        const int row = brow + tRow + i;
#pragma unroll
        for (int j = 0; j < TN; j += 4) {
            float4 v;
            if (MODE == 1) {
                const float skv = aux1[(long long)blockIdx.z * M + row];
                const int col = bcol + tCol + j;
                v.x = fmaxf(acc[i][j + 0] * skv * aux2[(long long)blockIdx.z * N + col + 0], 0.f);
                v.y = fmaxf(acc[i][j + 1] * skv * aux2[(long long)blockIdx.z * N + col + 1], 0.f);
                v.z = fmaxf(acc[i][j + 2] * skv * aux2[(long long)blockIdx.z * N + col + 2], 0.f);
                v.w = fmaxf(acc[i][j + 3] * skv * aux2[(long long)blockIdx.z * N + col + 3], 0.f);
            } else {
                v.x = acc[i][j + 0]; v.y = acc[i][j + 1];
                v.z = acc[i][j + 2]; v.w = acc[i][j + 3];
            }
            *reinterpret_cast<float4*>(&C[(long long)row * N + bcol + tCol + j]) = v;
        }
    }
}

// q = relu(qr) * relu(qi), written back over qr. Vectorized float4.
__global__ void relu_prod4(const float4* __restrict__ a,
                           const float4* __restrict__ b,
                           float4* __restrict__ c, long long n4)
{
    long long i = (long long)blockIdx.x * blockDim.x + threadIdx.x;
    if (i < n4) {
        float4 av = a[i], bv = b[i], o;
        o.x = fmaxf(av.x, 0.f) * fmaxf(bv.x, 0.f);
        o.y = fmaxf(av.y, 0.f) * fmaxf(bv.y, 0.f);
        o.z = fmaxf(av.z, 0.f) * fmaxf(bv.z, 0.f);
        o.w = fmaxf(av.w, 0.f) * fmaxf(bv.w, 0.f);
        c[i] = o;
    }
}

// Per-(b, e) inverse L2 norm over the sequence axis:
//   S[b*D + e] = 1 / (sqrt(sum_n X[b,n,e]^2) + EPS)
// grid: (D/32, B), 256 threads = 32 e-lanes x 8 n-slices (coalesced 128B lines).
__global__ void col_scale(const float* __restrict__ X, float* __restrict__ S)
{
    __shared__ float red[256];
    const int eo = threadIdx.x & 31;
    const int ns = threadIdx.x >> 5;
    const int e  = blockIdx.x * 32 + eo;
    const int b  = blockIdx.y;
    const float* p = X + (long long)b * NSEQ * DMODEL + e;
    float s = 0.f;
    for (int n = ns; n < NSEQ; n += 8) {
        float v = p[(long long)n * DMODEL];
        s += v * v;
    }
    red[threadIdx.x] = s;
    __syncthreads();
    if (ns == 0) {
        float t = 0.f;
#pragma unroll
        for (int i = 0; i < 8; ++i) t += red[i * 32 + eo];
        S[b * DMODEL + e] = 1.f / (sqrtf(t) + EPSC);
    }
}

// ---------------------------------------------------------------------------
// Launch
// ---------------------------------------------------------------------------
extern "C" void kernel_launch(void* const* d_in, const int* in_sizes, int n_in,
                              void* d_out, int out_size)
{
    const float* x   = (const float*)d_in[0];
    const float* wqr = (const float*)d_in[1];
    const float* wqi = (const float*)d_in[2];
    const float* wk  = (const float*)d_in[3];
    const float* wv  = (const float*)d_in[4];
    float* out = (float*)d_out;

    float *qr, *qi, *k, *v, *kv, *sk, *sv;
    cudaGetSymbolAddress((void**)&qr, g_qr);
    cudaGetSymbolAddress((void**)&qi, g_qi);
    cudaGetSymbolAddress((void**)&k,  g_k);
    cudaGetSymbolAddress((void**)&v,  g_v);
    cudaGetSymbolAddress((void**)&kv, g_kv);
    cudaGetSymbolAddress((void**)&sk, g_sk);
    cudaGetSymbolAddress((void**)&sv, g_sv);

    const int M1 = BSZ * NSEQ;   // 32768
    const int D  = DMODEL;       // 1024

    // Stage 1: four projections of x. [32768,1024] @ [1024,1024]
    dim3 g1(D / BN, M1 / BM, 1);
    sgemm_nn<0><<<g1, 256>>>(x, wqr, qr, M1, D, D, 0, 0, 0, nullptr, nullptr);
    sgemm_nn<0><<<g1, 256>>>(x, wqi, qi, M1, D, D, 0, 0, 0, nullptr, nullptr);
    sgemm_nn<0><<<g1, 256>>>(x, wk,  k,  M1, D, D, 0, 0, 0, nullptr, nullptr);
    sgemm_nn<0><<<g1, 256>>>(x, wv,  v,  M1, D, D, 0, 0, 0, nullptr, nullptr);

    // Stage 2: q = relu(qr)*relu(qi)  (in place over qr)
    const long long n4 = (long long)XELEMS / 4;   // 8388608
    relu_prod4<<<(unsigned)(n4 / 256), 256>>>((const float4*)qr, (const float4*)qi,
                                              (float4*)qr, n4);

    // Stage 3: per-(b,e) inverse norms of k and v over sequence axis
    dim3 gs(D / 32, BSZ);
    col_scale<<<gs, 256>>>(k, sk);
    col_scale<<<gs, 256>>>(v, sv);

    // Stage 4: kv[b] = relu( (K^T V) * sk ⊗ sv ), batched TN GEMM
    // A = k[b]: [NSEQ, D] row-major treated as [K=NSEQ, M=D]
    dim3 g2(D / BN, D / BM, BSZ);
    sgemm_tn<1><<<g2, 256>>>(k, v, kv, D, D, NSEQ,
                             (long long)NSEQ * D, (long long)NSEQ * D,
                             (long long)D * D, sk, sv);

    // Stage 5: out[b] = q[b] @ kv[b], batched NN GEMM
    dim3 g4(D / BN, NSEQ / BM, BSZ);
    sgemm_nn<0><<<g4, 256>>>(qr, kv, out, NSEQ, D, D,
                             (long long)NSEQ * D, (long long)D * D,
                             (long long)NSEQ * D, nullptr, nullptr);
}

// round 4
// speedup vs baseline: 2.0251x; 2.0251x over previous
#include <cuda_runtime.h>
#include <cstdint>
#include <math.h>

#define BSZ   8
#define NSEQ  4096
#define DM    1024
#define EPSC  1e-5f

// ---------------------------------------------------------------------------
// Scratch (device globals)
// ---------------------------------------------------------------------------
#define XELEMS (8u * 4096u * 1024u)
__device__ float g_qr[XELEMS];
__device__ float g_qi[XELEMS];
__device__ float g_k [XELEMS];
__device__ float g_v [XELEMS];
__device__ float g_kv[8u * 1024u * 1024u];
__device__ float g_sk[8u * 1024u];
__device__ float g_sv[8u * 1024u];

// ---------------------------------------------------------------------------
// Helpers
// ---------------------------------------------------------------------------
__device__ __forceinline__ uint32_t smem_u32(const void* p) {
    uint32_t a;
    asm("{ .reg .u64 t; cvta.to.shared.u64 t, %1; cvt.u32.u64 %0, t; }" : "=r"(a) : "l"(p));
    return a;
}
__device__ __forceinline__ void sts32(uint32_t a, uint32_t x) {
    asm volatile("st.shared.b32 [%0], %1;" :: "r"(a), "r"(x));
}
__device__ __forceinline__ void sts64(uint32_t a, uint32_t x, uint32_t y) {
    asm volatile("st.shared.v2.b32 [%0], {%1, %2};" :: "r"(a), "r"(x), "r"(y));
}
__device__ __forceinline__ uint32_t pack2(float lo, float hi) {  // lo -> low half
    uint32_t r;
    asm("cvt.rn.bf16x2.f32 %0, %1, %2;" : "=r"(r) : "f"(hi), "f"(lo));
    return r;
}
__device__ __forceinline__ void split2(float x, float y, uint32_t& h, uint32_t& l) {
    h = pack2(x, y);
    float hx = __uint_as_float(h << 16);
    float hy = __uint_as_float(h & 0xFFFF0000u);
    l = pack2(x - hx, y - hy);
}
__device__ __forceinline__ void ldm_x4(uint32_t* d, uint32_t a) {
    asm volatile("ldmatrix.sync.aligned.m8n8.x4.shared.b16 {%0,%1,%2,%3}, [%4];"
                 : "=r"(d[0]), "=r"(d[1]), "=r"(d[2]), "=r"(d[3]) : "r"(a));
}
__device__ __forceinline__ void ldm_x4t(uint32_t* d, uint32_t a) {
    asm volatile("ldmatrix.sync.aligned.m8n8.x4.trans.shared.b16 {%0,%1,%2,%3}, [%4];"
                 : "=r"(d[0]), "=r"(d[1]), "=r"(d[2]), "=r"(d[3]) : "r"(a));
}
__device__ __forceinline__ void mma16816(float* d, const uint32_t* a, const uint32_t* b) {
    asm volatile("mma.sync.aligned.m16n8k16.row.col.f32.bf16.bf16.f32 "
                 "{%0,%1,%2,%3}, {%4,%5,%6,%7}, {%8,%9}, {%0,%1,%2,%3};"
                 : "+f"(d[0]), "+f"(d[1]), "+f"(d[2]), "+f"(d[3])
                 : "r"(a[0]), "r"(a[1]), "r"(a[2]), "r"(a[3]), "r"(b[0]), "r"(b[1]));
}

// ---------------------------------------------------------------------------
// bf16x3 HMMA GEMM: C[M,N] = sum_k A[m,k]*B[n... wait B is [K,N]] fp32 in/out.
// BM=BN=128, BK=32, 256 threads, 8 warps (4 m x 2 n), warp tile 32x64.
// A smem tile: [128 m][32 k] bf16, 64B rows, chunk swizzle ^(row&3)
// B smem tile: [32 k][128 n] bf16, 256B rows, chunk swizzle ^(k&7)
// TRA=false: A gmem [M,K] row-major (k contiguous)
// TRA=true : A gmem [K,M] row-major (m contiguous) -> register transpose
// B gmem always [K,N] row-major (n contiguous)
// MODE 1: C = relu(acc * aux1[z*DM+row] * aux2[z*DM+col])
// ---------------------------------------------------------------------------
#define BM  128
#define BN  128
#define BKC 32
#define ABYTES 8192u
#define BUFBYTES 32768u
#define SMEM_BYTES 65536

template <bool TRA, int MODE>
__global__ __launch_bounds__(256)
void tgemm(const float* __restrict__ Ab, const float* __restrict__ Bb, float* __restrict__ Cb,
           int K, int lda, int ldb, int ldc,
           long long sA, long long sB, long long sC,
           const float* __restrict__ aux1, const float* __restrict__ aux2)
{
    extern __shared__ char smem[];
    const uint32_t sb = smem_u32(smem);
    const int tid = threadIdx.x;
    const int wid = tid >> 5, lid = tid & 31;
    const int z = blockIdx.z;
    const int brow = blockIdx.y * BM;
    const int bcol = blockIdx.x * BN;
    const float* A = Ab + (long long)z * sA;
    const float* B = Bb + (long long)z * sB;
    float* C = Cb + (long long)z * sC;

    const int wm = wid & 3;           // 0..3 -> m warp
    const int wn = wid >> 2;          // 0..1 -> n warp
    const int m0 = wm * 32;
    const int n0 = wn * 64;

    // ---- gmem load indices (per thread) ----
    // direct A: 4 float4: row = rA0 + i*32, k byte col c4a*4
    const int rA0 = tid >> 3, c4a = tid & 7;
    // trans A: 2 units: kp = kp0 + u*8, m4 fixed; loads rows 2kp,2kp+1
    const int kp0 = tid >> 5, m4 = tid & 31;
    // B: 4 float4: k = kB0 + i*8, n col c4b*4
    const int kB0 = tid >> 5, c4b = tid & 31;

    // ---- smem store addresses (fixed parts) ----
    // direct A: phys = row*64 + ((chunk ^ (row&3))<<4) + (c4a&1)*8 ; chunk=c4a>>1
    // B: phys = k*256 + (((c4b>>1) ^ (k&7))<<4) + (c4b&1)*8

    float4 regA[4];
    float4 regB[4];

    auto ldg_tile = [&](int c) {
        if (TRA) {
            // A[K,M]: rows k = c*32 + 2*kp(+1), col m = brow + m4*4
#pragma unroll
            for (int u = 0; u < 2; ++u) {
                int kp = kp0 + u * 8;
                const float* p = A + (long long)(c * BKC + 2 * kp) * lda + brow + m4 * 4;
                regA[2 * u]     = *(const float4*)p;
                regA[2 * u + 1] = *(const float4*)(p + lda);
            }
        } else {
#pragma unroll
            for (int i = 0; i < 4; ++i) {
                regA[i] = *(const float4*)(A + (long long)(brow + rA0 + i * 32) * lda
                                           + c * BKC + c4a * 4);
            }
        }
#pragma unroll
        for (int i = 0; i < 4; ++i) {
            regB[i] = *(const float4*)(B + (long long)(c * BKC + kB0 + i * 8) * ldb
                                       + bcol + c4b * 4);
        }
    };

    auto sts_tile = [&](int buf) {
        const uint32_t ah = sb + buf * BUFBYTES;
        const uint32_t al = ah + ABYTES;
        const uint32_t bh = ah + 2 * ABYTES;
        const uint32_t bl = ah + 3 * ABYTES;
        if (TRA) {
#pragma unroll
            for (int u = 0; u < 2; ++u) {
                int kp = kp0 + u * 8;
                const float* v0 = (const float*)&regA[2 * u];
                const float* v1 = (const float*)&regA[2 * u + 1];
                uint32_t chunk = kp >> 2;
                uint32_t within = (kp & 3) * 4;
#pragma unroll
                for (int j = 0; j < 4; ++j) {
                    int m = m4 * 4 + j;
                    uint32_t h, l;
                    split2(v0[j], v1[j], h, l);
                    uint32_t off = m * 64 + ((chunk ^ (m & 3)) << 4) + within;
                    sts32(ah + off, h);
                    sts32(al + off, l);
                }
            }
        } else {
            uint32_t chunk = c4a >> 1;
            uint32_t within = (c4a & 1) * 8;
#pragma unroll
            for (int i = 0; i < 4; ++i) {
                int row = rA0 + i * 32;
                uint32_t h0, l0, h1, l1;
                split2(regA[i].x, regA[i].y, h0, l0);
                split2(regA[i].z, regA[i].w, h1, l1);
                uint32_t off = row * 64 + ((chunk ^ (row & 3)) << 4) + within;
                sts64(ah + off, h0, h1);
                sts64(al + off, l0, l1);
            }
        }
        {
            uint32_t chunk = c4b >> 1;
            uint32_t within = (c4b & 1) * 8;
#pragma unroll
            for (int i = 0; i < 4; ++i) {
                int k = kB0 + i * 8;
                uint32_t h0, l0, h1, l1;
                split2(regB[i].x, regB[i].y, h0, l0);
                split2(regB[i].z, regB[i].w, h1, l1);
                uint32_t off = k * 256 + (((chunk) ^ (k & 7)) << 4) + within;
                sts64(bh + off, h0, h1);
                sts64(bl + off, l0, l1);
            }
        }
    };

    float acc[2][8][4];
#pragma unroll
    for (int a = 0; a < 2; ++a)
#pragma unroll
        for (int b = 0; b < 8; ++b)
#pragma unroll
            for (int d = 0; d < 4; ++d) acc[a][b][d] = 0.f;

    // per-lane ldmatrix address components
    const int la = lid & 15;          // A row within m16
    const int lah = lid >> 4;         // A k-chunk select
    const int lbk = (lid & 7) + (lid & 8);   // B k row within k16
    const int lbh = lid >> 4;         // B n-chunk select

    auto compute = [&](int buf) {
        const uint32_t ah = sb + buf * BUFBYTES;
        const uint32_t al = ah + ABYTES;
        const uint32_t bh = ah + 2 * ABYTES;
        const uint32_t bl = ah + 3 * ABYTES;
#pragma unroll
        for (int ks = 0; ks < 2; ++ks) {      // k16 step, k0 = ks*16
            uint32_t afh[2][4], afl[2][4], bfh[8][2], bfl[8][2];
#pragma unroll
            for (int mi = 0; mi < 2; ++mi) {
                int row = m0 + mi * 16 + la;
                uint32_t chunk = (ks * 2) + lah;    // k byte = ks*32 + lah*16
                uint32_t off = row * 64 + ((chunk ^ (row & 3)) << 4);
                ldm_x4(afh[mi], ah + off);
                ldm_x4(afl[mi], al + off);
            }
#pragma unroll
            for (int ni = 0; ni < 4; ++ni) {
                int krow = ks * 16 + lbk;
                uint32_t chunk = ((n0 + ni * 16) >> 3) + lbh;
                uint32_t off = krow * 256 + ((chunk ^ (krow & 7)) << 4);
                uint32_t t0[4], t1[4];
                ldm_x4t(t0, bh + off);
                ldm_x4t(t1, bl + off);
                bfh[ni * 2][0] = t0[0]; bfh[ni * 2][1] = t0[1];
                bfh[ni * 2 + 1][0] = t0[2]; bfh[ni * 2 + 1][1] = t0[3];
                bfl[ni * 2][0] = t1[0]; bfl[ni * 2][1] = t1[1];
                bfl[ni * 2 + 1][0] = t1[2]; bfl[ni * 2 + 1][1] = t1[3];
            }
#pragma unroll
            for (int mi = 0; mi < 2; ++mi)
#pragma unroll
                for (int n8 = 0; n8 < 8; ++n8) {
                    mma16816(acc[mi][n8], afh[mi], bfh[n8]);
                    mma16816(acc[mi][n8], afh[mi], bfl[n8]);
                    mma16816(acc[mi][n8], afl[mi], bfh[n8]);
                }
        }
    };

    const int NC = K / BKC;
    ldg_tile(0);
    sts_tile(0);
    __syncthreads();

    for (int c = 0; c < NC; ++c) {
        const int buf = c & 1;
        if (c + 1 < NC) ldg_tile(c + 1);
        compute(buf);
        if (c + 1 < NC) {
            __syncthreads();
            sts_tile(buf ^ 1);
            __syncthreads();
        }
    }

    // ---- epilogue ----
    const int r0 = lid >> 2;
    const int c0 = (lid & 3) * 2;
#pragma unroll
    for (int mi = 0; mi < 2; ++mi) {
#pragma unroll
        for (int half = 0; half < 2; ++half) {
            const int row = brow + m0 + mi * 16 + r0 + half * 8;
            float s1 = 1.f;
            if (MODE == 1) s1 = aux1[(long long)z * DM + row];
            float* cp = C + (long long)row * ldc + bcol + n0 + c0;
#pragma unroll
            for (int n8 = 0; n8 < 8; ++n8) {
                float d0 = acc[mi][n8][half * 2];
                float d1 = acc[mi][n8][half * 2 + 1];
                if (MODE == 1) {
                    const int col = bcol + n0 + n8 * 8 + c0;
                    d0 = fmaxf(d0 * s1 * aux2[(long long)z * DM + col], 0.f);
                    d1 = fmaxf(d1 * s1 * aux2[(long long)z * DM + col + 1], 0.f);
                }
                *(float2*)(cp + n8 * 8) = make_float2(d0, d1);
            }
        }
    }
}

// ---------------------------------------------------------------------------
// Elementwise helpers
// ---------------------------------------------------------------------------
__global__ void relu_prod4(const float4* __restrict__ a, const float4* __restrict__ b,
                           float4* __restrict__ c, long long n4)
{
    long long i = (long long)blockIdx.x * blockDim.x + threadIdx.x;
    if (i < n4) {
        float4 av = a[i], bv = b[i], o;
        o.x = fmaxf(av.x, 0.f) * fmaxf(bv.x, 0.f);
        o.y = fmaxf(av.y, 0.f) * fmaxf(bv.y, 0.f);
        o.z = fmaxf(av.z, 0.f) * fmaxf(bv.z, 0.f);
        o.w = fmaxf(av.w, 0.f) * fmaxf(bv.w, 0.f);
        c[i] = o;
    }
}

__global__ void col_scale(const float* __restrict__ X, float* __restrict__ S)
{
    __shared__ float red[256];
    const int eo = threadIdx.x & 31;
    const int ns = threadIdx.x >> 5;
    const int e  = blockIdx.x * 32 + eo;
    const int b  = blockIdx.y;
    const float* p = X + (long long)b * NSEQ * DM + e;
    float s = 0.f;
    for (int n = ns; n < NSEQ; n += 8) {
        float v = p[(long long)n * DM];
        s += v * v;
    }
    red[threadIdx.x] = s;
    __syncthreads();
    if (ns == 0) {
        float t = 0.f;
#pragma unroll
        for (int i = 0; i < 8; ++i) t += red[i * 32 + eo];
        S[b * DM + e] = 1.f / (sqrtf(t) + EPSC);
    }
}

// ---------------------------------------------------------------------------
// Launch
// ---------------------------------------------------------------------------
extern "C" void kernel_launch(void* const* d_in, const int* in_sizes, int n_in,
                              void* d_out, int out_size)
{
    const float* x   = (const float*)d_in[0];
    const float* wqr = (const float*)d_in[1];
    const float* wqi = (const float*)d_in[2];
    const float* wk  = (const float*)d_in[3];
    const float* wv  = (const float*)d_in[4];
    float* out = (float*)d_out;

    float *qr, *qi, *k, *v, *kv, *sk, *sv;
    cudaGetSymbolAddress((void**)&qr, g_qr);
    cudaGetSymbolAddress((void**)&qi, g_qi);
    cudaGetSymbolAddress((void**)&k,  g_k);
    cudaGetSymbolAddress((void**)&v,  g_v);
    cudaGetSymbolAddress((void**)&kv, g_kv);
    cudaGetSymbolAddress((void**)&sk, g_sk);
    cudaGetSymbolAddress((void**)&sv, g_sv);

    cudaFuncSetAttribute(tgemm<false, 0>, cudaFuncAttributeMaxDynamicSharedMemorySize, SMEM_BYTES);
    cudaFuncSetAttribute(tgemm<true, 1>,  cudaFuncAttributeMaxDynamicSharedMemorySize, SMEM_BYTES);

    // Stage 1: four projections. C[32768,1024] = x @ W
    dim3 g1(DM / BN, (BSZ * NSEQ) / BM, 1);
    tgemm<false, 0><<<g1, 256, SMEM_BYTES>>>(x, wqr, qr, DM, DM, DM, DM, 0, 0, 0, nullptr, nullptr);
    tgemm<false, 0><<<g1, 256, SMEM_BYTES>>>(x, wqi, qi, DM, DM, DM, DM, 0, 0, 0, nullptr, nullptr);
    tgemm<false, 0><<<g1, 256, SMEM_BYTES>>>(x, wk,  k,  DM, DM, DM, DM, 0, 0, 0, nullptr, nullptr);
    tgemm<false, 0><<<g1, 256, SMEM_BYTES>>>(x, wv,  v,  DM, DM, DM, DM, 0, 0, 0, nullptr, nullptr);

    // Stage 2: q = relu(qr)*relu(qi) in place over qr
    const long long n4 = (long long)XELEMS / 4;
    relu_prod4<<<(unsigned)(n4 / 256), 256>>>((const float4*)qr, (const float4*)qi, (float4*)qr, n4);

    // Stage 3: inverse L2 norms over sequence axis
    dim3 gs(DM / 32, BSZ);
    col_scale<<<gs, 256>>>(k, sk);
    col_scale<<<gs, 256>>>(v, sv);

    // Stage 4: kv[b] = relu((K^T V) .* sk x sv); A = k (trans), B = v (direct)
    dim3 g2(DM / BN, DM / BM, BSZ);
    tgemm<true, 1><<<g2, 256, SMEM_BYTES>>>(k, v, kv, NSEQ, DM, DM, DM,
                                            (long long)NSEQ * DM, (long long)NSEQ * DM,
                                            (long long)DM * DM, sk, sv);

    // Stage 5: out[b] = q[b] @ kv[b]; both direct
    dim3 g3(DM / BN, NSEQ / BM, BSZ);
    tgemm<false, 0><<<g3, 256, SMEM_BYTES>>>(qr, kv, out, DM, DM, DM, DM,
                                             (long long)NSEQ * DM, (long long)DM * DM,
                                             (long long)NSEQ * DM, nullptr, nullptr);
}

// round 5
// speedup vs baseline: 2.8021x; 1.3837x over previous
#include <cuda_runtime.h>
#include <cstdint>
#include <math.h>

#define BSZ   8
#define NSEQ  4096
#define DM    1024
#define EPSC  1e-5f

// ---------------------------------------------------------------------------
// Scratch (device globals). bf16 stored as uint16_t.
// ---------------------------------------------------------------------------
#define XELEMS (8u * 4096u * 1024u)
__device__ uint16_t g_xh[XELEMS],  g_xl[XELEMS];
__device__ uint16_t g_qrh[XELEMS], g_qrl[XELEMS];   // stage1 out; later q hi/lo
__device__ uint16_t g_qih[XELEMS], g_qil[XELEMS];
__device__ uint16_t g_kh[XELEMS],  g_kl[XELEMS];
__device__ uint16_t g_vh[XELEMS],  g_vl[XELEMS];
__device__ uint16_t g_wh[4u * 1048576u], g_wl[4u * 1048576u];
__device__ uint16_t g_kvh[8u * 1048576u], g_kvl[8u * 1048576u];
__device__ float    g_sk[8u * 1024u], g_sv[8u * 1024u];

// ---------------------------------------------------------------------------
// Helpers
// ---------------------------------------------------------------------------
__device__ __forceinline__ uint32_t smem_u32(const void* p) {
    uint32_t a;
    asm("{ .reg .u64 t; cvta.to.shared.u64 t, %1; cvt.u32.u64 %0, t; }" : "=r"(a) : "l"(p));
    return a;
}
__device__ __forceinline__ uint32_t pack2(float lo, float hi) {  // lo -> low half
    uint32_t r;
    asm("cvt.rn.bf16x2.f32 %0, %1, %2;" : "=r"(r) : "f"(hi), "f"(lo));
    return r;
}
__device__ __forceinline__ float blo(uint32_t u) { return __uint_as_float(u << 16); }
__device__ __forceinline__ float bhi(uint32_t u) { return __uint_as_float(u & 0xFFFF0000u); }
__device__ __forceinline__ void split2(float x, float y, uint32_t& h, uint32_t& l) {
    h = pack2(x, y);
    l = pack2(x - blo(h), y - bhi(h));
}
__device__ __forceinline__ void ldm_x4(uint32_t* d, uint32_t a) {
    asm volatile("ldmatrix.sync.aligned.m8n8.x4.shared.b16 {%0,%1,%2,%3}, [%4];"
                 : "=r"(d[0]), "=r"(d[1]), "=r"(d[2]), "=r"(d[3]) : "r"(a));
}
__device__ __forceinline__ void ldm_x4t(uint32_t* d, uint32_t a) {
    asm volatile("ldmatrix.sync.aligned.m8n8.x4.trans.shared.b16 {%0,%1,%2,%3}, [%4];"
                 : "=r"(d[0]), "=r"(d[1]), "=r"(d[2]), "=r"(d[3]) : "r"(a));
}
__device__ __forceinline__ void mma16816(float* d, const uint32_t* a, const uint32_t* b) {
    asm volatile("mma.sync.aligned.m16n8k16.row.col.f32.bf16.bf16.f32 "
                 "{%0,%1,%2,%3}, {%4,%5,%6,%7}, {%8,%9}, {%0,%1,%2,%3};"
                 : "+f"(d[0]), "+f"(d[1]), "+f"(d[2]), "+f"(d[3])
                 : "r"(a[0]), "r"(a[1]), "r"(a[2]), "r"(a[3]), "r"(b[0]), "r"(b[1]));
}
__device__ __forceinline__ void cpa16(uint32_t s, const void* g) {
    asm volatile("cp.async.cg.shared.global [%0], [%1], 16;" :: "r"(s), "l"(g));
}

// ---------------------------------------------------------------------------
// bf16x3 HMMA GEMM, pre-split operands, cp.async 3-stage pipeline.
// BM=BN=128, BK=32, 256 threads, warps 4m x 2n, warp tile 32x64.
// A smem (direct): [128 m][32 k], 64B rows, chunk^(m&3) swizzle
// A smem (TRA)  : [32 k][128 m], 256B rows, chunk^(k&7) swizzle
// B smem        : [32 k][128 n], 256B rows, chunk^(k&7) swizzle
// TRA=false: A gmem [M,K] (k contiguous). TRA=true: A gmem [K,M] (m contiguous).
// B gmem always [K,N] (n contiguous).
// MODE 0: fp32 C.  MODE 1: split bf16 -> (Ch, Cl).  MODE 2: scale+relu+split.
// ---------------------------------------------------------------------------
#define BM  128
#define BN  128
#define BKC 32
#define STG_BYTES 32768u
#define SMEM_BYTES 98304

template <bool TRA, int MODE>
__global__ __launch_bounds__(256, 2)
void tgemm(const uint16_t* __restrict__ Ah, const uint16_t* __restrict__ Al,
           const uint16_t* __restrict__ Bh, const uint16_t* __restrict__ Bl,
           void* __restrict__ C0, void* __restrict__ C1,
           int K, int lda, int ldb, int ldc,
           long long sA, long long sB, long long sC,
           const float* __restrict__ aux1, const float* __restrict__ aux2)
{
    extern __shared__ char smem[];
    const uint32_t sb = smem_u32(smem);
    const int tid = threadIdx.x;
    const int wid = tid >> 5, lid = tid & 31;
    const int z = blockIdx.z;
    const int brow = blockIdx.y * BM;
    const int bcol = blockIdx.x * BN;
    const uint16_t* A_h = Ah + z * sA;
    const uint16_t* A_l = Al + z * sA;
    const uint16_t* B_h = Bh + z * sB;
    const uint16_t* B_l = Bl + z * sB;

    const int m0 = (wid & 3) * 32;
    const int n0 = (wid >> 2) * 64;

    float acc[2][8][4];
#pragma unroll
    for (int a = 0; a < 2; ++a)
#pragma unroll
        for (int b = 0; b < 8; ++b)
#pragma unroll
            for (int d = 0; d < 4; ++d) acc[a][b][d] = 0.f;

    const int NC = K / BKC;

    auto issue = [&](int c) {
        const uint32_t st = sb + (uint32_t)(c % 3) * STG_BYTES;
        const int koff = c * BKC;
        if (TRA) {
#pragma unroll
            for (int i = 0; i < 2; ++i) {
                int idx = tid + i * 256;
                int kk = idx >> 4, cc = idx & 15;
                int g = (koff + kk) * lda + brow + cc * 8;
                uint32_t off = kk * 256 + (((uint32_t)(cc ^ (kk & 7))) << 4);
                cpa16(st + off,         A_h + g);
                cpa16(st + 8192 + off,  A_l + g);
            }
        } else {
#pragma unroll
            for (int i = 0; i < 2; ++i) {
                int idx = tid + i * 256;
                int m = idx >> 2, cc = idx & 3;
                int g = (brow + m) * lda + koff + cc * 8;
                uint32_t off = m * 64 + (((uint32_t)(cc ^ (m & 3))) << 4);
                cpa16(st + off,         A_h + g);
                cpa16(st + 8192 + off,  A_l + g);
            }
        }
#pragma unroll
        for (int i = 0; i < 2; ++i) {
            int idx = tid + i * 256;
            int kk = idx >> 4, cc = idx & 15;
            int g = (koff + kk) * ldb + bcol + cc * 8;
            uint32_t off = kk * 256 + (((uint32_t)(cc ^ (kk & 7))) << 4);
            cpa16(st + 16384 + off, B_h + g);
            cpa16(st + 24576 + off, B_l + g);
        }
        asm volatile("cp.async.commit_group;" ::: "memory");
    };

    auto compute = [&](int c) {
        const uint32_t st = sb + (uint32_t)(c % 3) * STG_BYTES;
#pragma unroll
        for (int ks = 0; ks < 2; ++ks) {
            uint32_t afh[2][4], afl[2][4];
#pragma unroll
            for (int mi = 0; mi < 2; ++mi) {
                if (TRA) {
                    int krow = ks * 16 + (lid & 7) + ((lid & 16) >> 1);
                    int ch = ((m0 + mi * 16) >> 3) + ((lid >> 3) & 1);
                    uint32_t off = krow * 256 + (((uint32_t)(ch ^ (krow & 7))) << 4);
                    ldm_x4t(afh[mi], st + off);
                    ldm_x4t(afl[mi], st + 8192 + off);
                } else {
                    int row = m0 + mi * 16 + (lid & 15);
                    int ch = ks * 2 + (lid >> 4);
                    uint32_t off = row * 64 + (((uint32_t)(ch ^ (row & 3))) << 4);
                    ldm_x4(afh[mi], st + off);
                    ldm_x4(afl[mi], st + 8192 + off);
                }
            }
#pragma unroll
            for (int ni = 0; ni < 4; ++ni) {
                int krow = ks * 16 + (lid & 7) + (lid & 8);
                int ch = ((n0 + ni * 16) >> 3) + (lid >> 4);
                uint32_t off = krow * 256 + (((uint32_t)(ch ^ (krow & 7))) << 4);
                uint32_t t0[4], t1[4];
                ldm_x4t(t0, st + 16384 + off);
                ldm_x4t(t1, st + 24576 + off);
#pragma unroll
                for (int mi = 0; mi < 2; ++mi) {
                    mma16816(acc[mi][ni * 2],     afh[mi], &t0[0]);
                    mma16816(acc[mi][ni * 2],     afh[mi], &t1[0]);
                    mma16816(acc[mi][ni * 2],     afl[mi], &t0[0]);
                    mma16816(acc[mi][ni * 2 + 1], afh[mi], &t0[2]);
                    mma16816(acc[mi][ni * 2 + 1], afh[mi], &t1[2]);
                    mma16816(acc[mi][ni * 2 + 1], afl[mi], &t0[2]);
                }
            }
        }
    };

    issue(0);
    issue(1);
    for (int c = 0; c < NC; ++c) {
        if (c + 2 < NC) {
            asm volatile("cp.async.wait_group 1;" ::: "memory");
        } else {
            asm volatile("cp.async.wait_group 0;" ::: "memory");
        }
        __syncthreads();
        if (c + 2 < NC) issue(c + 2);
        compute(c);
    }

    // ---- epilogue ----
    const int r0 = lid >> 2;
    const int c0 = (lid & 3) * 2;
#pragma unroll
    for (int mi = 0; mi < 2; ++mi) {
#pragma unroll
        for (int half = 0; half < 2; ++half) {
            const int row = brow + m0 + mi * 16 + r0 + half * 8;
            float s1 = 1.f;
            if (MODE == 2) s1 = aux1[z * DM + row];
#pragma unroll
            for (int n8 = 0; n8 < 8; ++n8) {
                float d0 = acc[mi][n8][half * 2];
                float d1 = acc[mi][n8][half * 2 + 1];
                const int col = bcol + n0 + n8 * 8 + c0;
                if (MODE == 2) {
                    d0 = fmaxf(d0 * s1 * aux2[z * DM + col], 0.f);
                    d1 = fmaxf(d1 * s1 * aux2[z * DM + col + 1], 0.f);
                }
                if (MODE == 0) {
                    float* C = (float*)C0 + z * sC;
                    *(float2*)(C + (long long)row * ldc + col) = make_float2(d0, d1);
                } else {
                    uint32_t h, l;
                    split2(d0, d1, h, l);
                    uint32_t* Ch = (uint32_t*)C0;
                    uint32_t* Cl = (uint32_t*)C1;
                    long long idx = ((long long)z * sC + (long long)row * ldc + col) >> 1;
                    Ch[idx] = h;
                    Cl[idx] = l;
                }
            }
        }
    }
}

// ---------------------------------------------------------------------------
// Elementwise kernels
// ---------------------------------------------------------------------------
// fp32 -> bf16 hi/lo split, 4 elems/thread
__global__ void split_pass(const float4* __restrict__ in, uint2* __restrict__ hi,
                           uint2* __restrict__ lo, int n4)
{
    int i = blockIdx.x * blockDim.x + threadIdx.x;
    if (i < n4) {
        float4 v = in[i];
        uint32_t h0, l0, h1, l1;
        split2(v.x, v.y, h0, l0);
        split2(v.z, v.w, h1, l1);
        hi[i] = make_uint2(h0, h1);
        lo[i] = make_uint2(l0, l1);
    }
}

// q = relu(qr)*relu(qi) from hi/lo pairs, output split hi/lo (in-place over qr ok)
__global__ void relu_prod_bf(const uint2* __restrict__ arh, const uint2* __restrict__ arl,
                             const uint2* __restrict__ aih, const uint2* __restrict__ ail,
                             uint2* __restrict__ oh, uint2* __restrict__ ol, int n4)
{
    int i = blockIdx.x * blockDim.x + threadIdx.x;
    if (i < n4) {
        uint2 rh = arh[i], rl = arl[i], ih = aih[i], il = ail[i];
        float a0 = blo(rh.x) + blo(rl.x), a1 = bhi(rh.x) + bhi(rl.x);
        float a2 = blo(rh.y) + blo(rl.y), a3 = bhi(rh.y) + bhi(rl.y);
        float b0 = blo(ih.x) + blo(il.x), b1 = bhi(ih.x) + bhi(il.x);
        float b2 = blo(ih.y) + blo(il.y), b3 = bhi(ih.y) + bhi(il.y);
        float q0 = fmaxf(a0, 0.f) * fmaxf(b0, 0.f);
        float q1 = fmaxf(a1, 0.f) * fmaxf(b1, 0.f);
        float q2 = fmaxf(a2, 0.f) * fmaxf(b2, 0.f);
        float q3 = fmaxf(a3, 0.f) * fmaxf(b3, 0.f);
        uint32_t h0, l0, h1, l1;
        split2(q0, q1, h0, l0);
        split2(q2, q3, h1, l1);
        oh[i] = make_uint2(h0, h1);
        ol[i] = make_uint2(l0, l1);
    }
}

// Per-(b,e) inverse L2 norm over sequence axis, from hi/lo bf16 arrays.
// 256 thr = 32 lanes (2 e each via u32) x 8 n-slices. grid (DM/64, BSZ).
__global__ void col_scale_bf(const uint32_t* __restrict__ Xh, const uint32_t* __restrict__ Xl,
                             float* __restrict__ S)
{
    __shared__ float red0[256], red1[256];
    const int lane = threadIdx.x & 31;
    const int sl = threadIdx.x >> 5;
    const int e2 = blockIdx.x * 32 + lane;      // u32 index: elems 2*e2, 2*e2+1
    const int b = blockIdx.y;
    const int base = b * (NSEQ * DM / 2) + e2;
    float s0 = 0.f, s1 = 0.f;
    for (int n = sl; n < NSEQ; n += 8) {
        uint32_t uh = Xh[base + n * (DM / 2)];
        uint32_t ul = Xl[base + n * (DM / 2)];
        float v0 = blo(uh) + blo(ul);
        float v1 = bhi(uh) + bhi(ul);
        s0 += v0 * v0;
        s1 += v1 * v1;
    }
    red0[threadIdx.x] = s0;
    red1[threadIdx.x] = s1;
    __syncthreads();
    if (sl == 0) {
        float t0 = 0.f, t1 = 0.f;
#pragma unroll
        for (int i = 0; i < 8; ++i) { t0 += red0[i * 32 + lane]; t1 += red1[i * 32 + lane]; }
        S[b * DM + e2 * 2]     = 1.f / (sqrtf(t0) + EPSC);
        S[b * DM + e2 * 2 + 1] = 1.f / (sqrtf(t1) + EPSC);
    }
}

// ---------------------------------------------------------------------------
// Launch
// ---------------------------------------------------------------------------
extern "C" void kernel_launch(void* const* d_in, const int* in_sizes, int n_in,
                              void* d_out, int out_size)
{
    const float* x   = (const float*)d_in[0];
    const float* wqr = (const float*)d_in[1];
    const float* wqi = (const float*)d_in[2];
    const float* wk  = (const float*)d_in[3];
    const float* wv  = (const float*)d_in[4];
    float* out = (float*)d_out;

    uint16_t *xh, *xl, *qrh, *qrl, *qih, *qil, *kh, *kl, *vh, *vl, *wh, *wl, *kvh, *kvl;
    float *sk, *sv;
    cudaGetSymbolAddress((void**)&xh,  g_xh);  cudaGetSymbolAddress((void**)&xl,  g_xl);
    cudaGetSymbolAddress((void**)&qrh, g_qrh); cudaGetSymbolAddress((void**)&qrl, g_qrl);
    cudaGetSymbolAddress((void**)&qih, g_qih); cudaGetSymbolAddress((void**)&qil, g_qil);
    cudaGetSymbolAddress((void**)&kh,  g_kh);  cudaGetSymbolAddress((void**)&kl,  g_kl);
    cudaGetSymbolAddress((void**)&vh,  g_vh);  cudaGetSymbolAddress((void**)&vl,  g_vl);
    cudaGetSymbolAddress((void**)&wh,  g_wh);  cudaGetSymbolAddress((void**)&wl,  g_wl);
    cudaGetSymbolAddress((void**)&kvh, g_kvh); cudaGetSymbolAddress((void**)&kvl, g_kvl);
    cudaGetSymbolAddress((void**)&sk,  g_sk);  cudaGetSymbolAddress((void**)&sv,  g_sv);

    cudaFuncSetAttribute(tgemm<false, 0>, cudaFuncAttributeMaxDynamicSharedMemorySize, SMEM_BYTES);
    cudaFuncSetAttribute(tgemm<false, 1>, cudaFuncAttributeMaxDynamicSharedMemorySize, SMEM_BYTES);
    cudaFuncSetAttribute(tgemm<true, 2>,  cudaFuncAttributeMaxDynamicSharedMemorySize, SMEM_BYTES);

    // Split inputs to bf16 hi/lo
    split_pass<<<XELEMS / 4 / 256, 256>>>((const float4*)x, (uint2*)xh, (uint2*)xl, XELEMS / 4);
    const int wn4 = 1048576 / 4;
    split_pass<<<wn4 / 256, 256>>>((const float4*)wqr, (uint2*)wh,               (uint2*)wl,               wn4);
    split_pass<<<wn4 / 256, 256>>>((const float4*)wqi, (uint2*)(wh + 1048576),   (uint2*)(wl + 1048576),   wn4);
    split_pass<<<wn4 / 256, 256>>>((const float4*)wk,  (uint2*)(wh + 2097152),   (uint2*)(wl + 2097152),   wn4);
    split_pass<<<wn4 / 256, 256>>>((const float4*)wv,  (uint2*)(wh + 3145728),   (uint2*)(wl + 3145728),   wn4);

    // Stage 1: four projections, split bf16 outputs
    dim3 g1(DM / BN, (BSZ * NSEQ) / BM, 1);
    tgemm<false, 1><<<g1, 256, SMEM_BYTES>>>(xh, xl, wh,             wl,             qrh, qrl,
                                             DM, DM, DM, DM, 0, 0, 0, nullptr, nullptr);
    tgemm<false, 1><<<g1, 256, SMEM_BYTES>>>(xh, xl, wh + 1048576,   wl + 1048576,   qih, qil,
                                             DM, DM, DM, DM, 0, 0, 0, nullptr, nullptr);
    tgemm<false, 1><<<g1, 256, SMEM_BYTES>>>(xh, xl, wh + 2097152,   wl + 2097152,   kh, kl,
                                             DM, DM, DM, DM, 0, 0, 0, nullptr, nullptr);
    tgemm<false, 1><<<g1, 256, SMEM_BYTES>>>(xh, xl, wh + 3145728,   wl + 3145728,   vh, vl,
                                             DM, DM, DM, DM, 0, 0, 0, nullptr, nullptr);

    // Stage 2: q = relu(qr)*relu(qi), split output in place over qr
    relu_prod_bf<<<XELEMS / 4 / 256, 256>>>((const uint2*)qrh, (const uint2*)qrl,
                                            (const uint2*)qih, (const uint2*)qil,
                                            (uint2*)qrh, (uint2*)qrl, XELEMS / 4);

    // Stage 3: inverse L2 norms
    dim3 gs(DM / 64, BSZ);
    col_scale_bf<<<gs, 256>>>((const uint32_t*)kh, (const uint32_t*)kl, sk);
    col_scale_bf<<<gs, 256>>>((const uint32_t*)vh, (const uint32_t*)vl, sv);

    // Stage 4: kv[b] = relu((K^T V) .* sk x sv), split output
    dim3 g2(DM / BN, DM / BM, BSZ);
    tgemm<true, 2><<<g2, 256, SMEM_BYTES>>>(kh, kl, vh, vl, kvh, kvl,
                                            NSEQ, DM, DM, DM,
                                            (long long)NSEQ * DM, (long long)NSEQ * DM,
                                            (long long)DM * DM, sk, sv);

    // Stage 5: out[b] = q[b] @ kv[b], fp32 output
    dim3 g3(DM / BN, NSEQ / BM, BSZ);
    tgemm<false, 0><<<g3, 256, SMEM_BYTES>>>(qrh, qrl, kvh, kvl, out, nullptr,
                                             DM, DM, DM, DM,
                                             (long long)NSEQ * DM, (long long)DM * DM,
                                             (long long)NSEQ * DM, nullptr, nullptr);
}

// round 6
// speedup vs baseline: 4.1970x; 1.4978x over previous
#include <cuda_runtime.h>
#include <cuda_fp16.h>
#include <cstdint>
#include <math.h>

#define BSZ   8
#define NSEQ  4096
#define DM    1024
#define EPSC  1e-5f

// ---------------------------------------------------------------------------
// Scratch (device globals). fp16 stored as uint16_t.
// ---------------------------------------------------------------------------
#define XELEMS (8u * 4096u * 1024u)
__device__ uint16_t g_xh[XELEMS], g_xl[XELEMS];    // x split; later reused for q split
__device__ float    g_qr[XELEMS];                  // stage1 qr (fp32)
__device__ float    g_qi[XELEMS];                  // stage1 qi (fp32)
__device__ uint16_t g_kh[XELEMS], g_kl[XELEMS];    // k split
__device__ uint16_t g_vh[XELEMS];                  // v single fp16
__device__ uint16_t g_wh[4u * 1048576u];           // 4 weights, single fp16
__device__ uint16_t g_kvh[8u * 1048576u];          // kv single fp16
__device__ float    g_sk[8u * 1024u], g_sv[8u * 1024u];

// ---------------------------------------------------------------------------
// Helpers
// ---------------------------------------------------------------------------
__device__ __forceinline__ uint32_t smem_u32(const void* p) {
    uint32_t a;
    asm("{ .reg .u64 t; cvta.to.shared.u64 t, %1; cvt.u32.u64 %0, t; }" : "=r"(a) : "l"(p));
    return a;
}
__device__ __forceinline__ uint32_t packh2(float x, float y) {
    __half2 h = __floats2half2_rn(x, y);
    return *reinterpret_cast<uint32_t*>(&h);
}
__device__ __forceinline__ float2 unpackh2(uint32_t u) {
    __half2 h = *reinterpret_cast<__half2*>(&u);
    return __half22float2(h);
}
__device__ __forceinline__ void splith2(float x, float y, uint32_t& h, uint32_t& l) {
    h = packh2(x, y);
    float2 f = unpackh2(h);
    l = packh2(x - f.x, y - f.y);
}
__device__ __forceinline__ void ldm_x4(uint32_t* d, uint32_t a) {
    asm volatile("ldmatrix.sync.aligned.m8n8.x4.shared.b16 {%0,%1,%2,%3}, [%4];"
                 : "=r"(d[0]), "=r"(d[1]), "=r"(d[2]), "=r"(d[3]) : "r"(a));
}
__device__ __forceinline__ void ldm_x4t(uint32_t* d, uint32_t a) {
    asm volatile("ldmatrix.sync.aligned.m8n8.x4.trans.shared.b16 {%0,%1,%2,%3}, [%4];"
                 : "=r"(d[0]), "=r"(d[1]), "=r"(d[2]), "=r"(d[3]) : "r"(a));
}
__device__ __forceinline__ void mma16816(float* d, const uint32_t* a, const uint32_t* b) {
    asm volatile("mma.sync.aligned.m16n8k16.row.col.f32.f16.f16.f32 "
                 "{%0,%1,%2,%3}, {%4,%5,%6,%7}, {%8,%9}, {%0,%1,%2,%3};"
                 : "+f"(d[0]), "+f"(d[1]), "+f"(d[2]), "+f"(d[3])
                 : "r"(a[0]), "r"(a[1]), "r"(a[2]), "r"(a[3]), "r"(b[0]), "r"(b[1]));
}
__device__ __forceinline__ void cpa16(uint32_t s, const void* g) {
    asm volatile("cp.async.cg.shared.global [%0], [%1], 16;" :: "r"(s), "l"(g));
}

// ---------------------------------------------------------------------------
// fp16x2 HMMA GEMM (A split hi/lo, B single), cp.async 4-stage pipeline.
// BM=BN=128, BK=32, 256 threads, warps 4m x 2n, warp tile 32x64.
// A smem (direct): [128 m][32 k], 64B rows, chunk^(m&3) swizzle
// A smem (TRA)   : [32 k][128 m], 256B rows, chunk^(k&7) swizzle
// B smem         : [32 k][128 n], 256B rows, chunk^(k&7) swizzle
// TRA=false: A gmem [M,K] (k contiguous). TRA=true: A gmem [K,M] (m contiguous).
// B gmem always [K,N] (n contiguous), fp16.
// MODE 0: fp32 C0.  MODE 1: split fp16 (C0=hi, C1=lo).
// MODE 2: single fp16 C0.  MODE 3: scale(aux1,aux2)+relu -> single fp16 C0.
// ---------------------------------------------------------------------------
#define BM  128
#define BN  128
#define BKC 32
#define STG_BYTES 24576u
#define SMEM_BYTES 98304

template <bool TRA, int MODE>
__global__ __launch_bounds__(256, 2)
void tgemm(const uint16_t* __restrict__ Ah, const uint16_t* __restrict__ Al,
           const uint16_t* __restrict__ Bp,
           void* __restrict__ C0, void* __restrict__ C1,
           int K, int lda, int ldb, int ldc,
           long long sA, long long sB, long long sC,
           const float* __restrict__ aux1, const float* __restrict__ aux2)
{
    extern __shared__ char smem[];
    const uint32_t sb = smem_u32(smem);
    const int tid = threadIdx.x;
    const int wid = tid >> 5, lid = tid & 31;
    const int z = blockIdx.z;
    const int brow = blockIdx.y * BM;
    const int bcol = blockIdx.x * BN;
    const uint16_t* A_h = Ah + z * sA;
    const uint16_t* A_l = Al + z * sA;
    const uint16_t* B_p = Bp + z * sB;

    const int m0 = (wid & 3) * 32;
    const int n0 = (wid >> 2) * 64;

    float acc[2][8][4];
#pragma unroll
    for (int a = 0; a < 2; ++a)
#pragma unroll
        for (int b = 0; b < 8; ++b)
#pragma unroll
            for (int d = 0; d < 4; ++d) acc[a][b][d] = 0.f;

    const int NC = K / BKC;

    auto issue = [&](int c) {
        const uint32_t st = sb + (uint32_t)(c & 3) * STG_BYTES;
        const int koff = c * BKC;
        if (TRA) {
#pragma unroll
            for (int i = 0; i < 2; ++i) {
                int idx = tid + i * 256;
                int kk = idx >> 4, cc = idx & 15;
                int g = (koff + kk) * lda + brow + cc * 8;
                uint32_t off = kk * 256 + (((uint32_t)(cc ^ (kk & 7))) << 4);
                cpa16(st + off,        A_h + g);
                cpa16(st + 8192 + off, A_l + g);
            }
        } else {
#pragma unroll
            for (int i = 0; i < 2; ++i) {
                int idx = tid + i * 256;
                int m = idx >> 2, cc = idx & 3;
                int g = (brow + m) * lda + koff + cc * 8;
                uint32_t off = m * 64 + (((uint32_t)(cc ^ (m & 3))) << 4);
                cpa16(st + off,        A_h + g);
                cpa16(st + 8192 + off, A_l + g);
            }
        }
#pragma unroll
        for (int i = 0; i < 2; ++i) {
            int idx = tid + i * 256;
            int kk = idx >> 4, cc = idx & 15;
            int g = (koff + kk) * ldb + bcol + cc * 8;
            uint32_t off = kk * 256 + (((uint32_t)(cc ^ (kk & 7))) << 4);
            cpa16(st + 16384 + off, B_p + g);
        }
        asm volatile("cp.async.commit_group;" ::: "memory");
    };

    auto compute = [&](int c) {
        const uint32_t st = sb + (uint32_t)(c & 3) * STG_BYTES;
#pragma unroll
        for (int ks = 0; ks < 2; ++ks) {
            uint32_t afh[2][4], afl[2][4];
#pragma unroll
            for (int mi = 0; mi < 2; ++mi) {
                if (TRA) {
                    int krow = ks * 16 + (lid & 7) + ((lid & 16) >> 1);
                    int ch = ((m0 + mi * 16) >> 3) + ((lid >> 3) & 1);
                    uint32_t off = krow * 256 + (((uint32_t)(ch ^ (krow & 7))) << 4);
                    ldm_x4t(afh[mi], st + off);
                    ldm_x4t(afl[mi], st + 8192 + off);
                } else {
                    int row = m0 + mi * 16 + (lid & 15);
                    int ch = ks * 2 + (lid >> 4);
                    uint32_t off = row * 64 + (((uint32_t)(ch ^ (row & 3))) << 4);
                    ldm_x4(afh[mi], st + off);
                    ldm_x4(afl[mi], st + 8192 + off);
                }
            }
#pragma unroll
            for (int ni = 0; ni < 4; ++ni) {
                int krow = ks * 16 + (lid & 7) + (lid & 8);
                int ch = ((n0 + ni * 16) >> 3) + (lid >> 4);
                uint32_t off = krow * 256 + (((uint32_t)(ch ^ (krow & 7))) << 4) + 16384;
                uint32_t t[4];
                ldm_x4t(t, st + off);
#pragma unroll
                for (int mi = 0; mi < 2; ++mi) {
                    mma16816(acc[mi][ni * 2],     afh[mi], &t[0]);
                    mma16816(acc[mi][ni * 2],     afl[mi], &t[0]);
                    mma16816(acc[mi][ni * 2 + 1], afh[mi], &t[2]);
                    mma16816(acc[mi][ni * 2 + 1], afl[mi], &t[2]);
                }
            }
        }
    };

    issue(0);
    issue(1);
    issue(2);
    for (int c = 0; c < NC; ++c) {
        const int pend = NC - 1 - c;
        if (pend >= 2)      asm volatile("cp.async.wait_group 2;" ::: "memory");
        else if (pend == 1) asm volatile("cp.async.wait_group 1;" ::: "memory");
        else                asm volatile("cp.async.wait_group 0;" ::: "memory");
        __syncthreads();
        if (c + 3 < NC) issue(c + 3);
        compute(c);
        __syncthreads();
    }

    // ---- epilogue ----
    const int r0 = lid >> 2;
    const int c0 = (lid & 3) * 2;
#pragma unroll
    for (int mi = 0; mi < 2; ++mi) {
#pragma unroll
        for (int half = 0; half < 2; ++half) {
            const int row = brow + m0 + mi * 16 + r0 + half * 8;
            float s1 = 1.f;
            if (MODE == 3) s1 = aux1[z * DM + row];
#pragma unroll
            for (int n8 = 0; n8 < 8; ++n8) {
                float d0 = acc[mi][n8][half * 2];
                float d1 = acc[mi][n8][half * 2 + 1];
                const int col = bcol + n0 + n8 * 8 + c0;
                if (MODE == 3) {
                    d0 = fmaxf(d0 * s1 * aux2[z * DM + col], 0.f);
                    d1 = fmaxf(d1 * s1 * aux2[z * DM + col + 1], 0.f);
                }
                long long lidx = (long long)z * sC + (long long)row * ldc + col;
                if (MODE == 0) {
                    *(float2*)((float*)C0 + lidx) = make_float2(d0, d1);
                } else if (MODE == 1) {
                    uint32_t h, l;
                    splith2(d0, d1, h, l);
                    ((uint32_t*)C0)[lidx >> 1] = h;
                    ((uint32_t*)C1)[lidx >> 1] = l;
                } else {
                    ((uint32_t*)C0)[lidx >> 1] = packh2(d0, d1);
                }
            }
        }
    }
}

// ---------------------------------------------------------------------------
// Elementwise kernels
// ---------------------------------------------------------------------------
// fp32 -> fp16 hi/lo split, 4 elems/thread
__global__ void split_x(const float4* __restrict__ in, uint2* __restrict__ hi,
                        uint2* __restrict__ lo, int n4)
{
    int i = blockIdx.x * blockDim.x + threadIdx.x;
    if (i < n4) {
        float4 v = in[i];
        uint32_t h0, l0, h1, l1;
        splith2(v.x, v.y, h0, l0);
        splith2(v.z, v.w, h1, l1);
        hi[i] = make_uint2(h0, h1);
        lo[i] = make_uint2(l0, l1);
    }
}

// fp32 -> fp16 single
__global__ void cvt_h(const float4* __restrict__ in, uint2* __restrict__ o, int n4)
{
    int i = blockIdx.x * blockDim.x + threadIdx.x;
    if (i < n4) {
        float4 v = in[i];
        o[i] = make_uint2(packh2(v.x, v.y), packh2(v.z, v.w));
    }
}

// q = relu(qr)*relu(qi) (fp32 in), split fp16 out
__global__ void relu_prod(const float4* __restrict__ ar, const float4* __restrict__ ai,
                          uint2* __restrict__ oh, uint2* __restrict__ ol, int n4)
{
    int i = blockIdx.x * blockDim.x + threadIdx.x;
    if (i < n4) {
        float4 r = ar[i], q = ai[i];
        float q0 = fmaxf(r.x, 0.f) * fmaxf(q.x, 0.f);
        float q1 = fmaxf(r.y, 0.f) * fmaxf(q.y, 0.f);
        float q2 = fmaxf(r.z, 0.f) * fmaxf(q.z, 0.f);
        float q3 = fmaxf(r.w, 0.f) * fmaxf(q.w, 0.f);
        uint32_t h0, l0, h1, l1;
        splith2(q0, q1, h0, l0);
        splith2(q2, q3, h1, l1);
        oh[i] = make_uint2(h0, h1);
        ol[i] = make_uint2(l0, l1);
    }
}

// inverse L2 norm over sequence axis from split fp16 (hi+lo)
__global__ void col_scale_sp(const uint32_t* __restrict__ Xh, const uint32_t* __restrict__ Xl,
                             float* __restrict__ S)
{
    __shared__ float red0[256], red1[256];
    const int lane = threadIdx.x & 31;
    const int sl = threadIdx.x >> 5;
    const int e2 = blockIdx.x * 32 + lane;
    const int b = blockIdx.y;
    const int base = b * (NSEQ * DM / 2) + e2;
    float s0 = 0.f, s1 = 0.f;
    for (int n = sl; n < NSEQ; n += 8) {
        float2 fh = unpackh2(Xh[base + n * (DM / 2)]);
        float2 fl = unpackh2(Xl[base + n * (DM / 2)]);
        float v0 = fh.x + fl.x, v1 = fh.y + fl.y;
        s0 += v0 * v0;
        s1 += v1 * v1;
    }
    red0[threadIdx.x] = s0;
    red1[threadIdx.x] = s1;
    __syncthreads();
    if (sl == 0) {
        float t0 = 0.f, t1 = 0.f;
#pragma unroll
        for (int i = 0; i < 8; ++i) { t0 += red0[i * 32 + lane]; t1 += red1[i * 32 + lane]; }
        S[b * DM + e2 * 2]     = 1.f / (sqrtf(t0) + EPSC);
        S[b * DM + e2 * 2 + 1] = 1.f / (sqrtf(t1) + EPSC);
    }
}

// inverse L2 norm from single fp16
__global__ void col_scale_h(const uint32_t* __restrict__ X, float* __restrict__ S)
{
    __shared__ float red0[256], red1[256];
    const int lane = threadIdx.x & 31;
    const int sl = threadIdx.x >> 5;
    const int e2 = blockIdx.x * 32 + lane;
    const int b = blockIdx.y;
    const int base = b * (NSEQ * DM / 2) + e2;
    float s0 = 0.f, s1 = 0.f;
    for (int n = sl; n < NSEQ; n += 8) {
        float2 f = unpackh2(X[base + n * (DM / 2)]);
        s0 += f.x * f.x;
        s1 += f.y * f.y;
    }
    red0[threadIdx.x] = s0;
    red1[threadIdx.x] = s1;
    __syncthreads();
    if (sl == 0) {
        float t0 = 0.f, t1 = 0.f;
#pragma unroll
        for (int i = 0; i < 8; ++i) { t0 += red0[i * 32 + lane]; t1 += red1[i * 32 + lane]; }
        S[b * DM + e2 * 2]     = 1.f / (sqrtf(t0) + EPSC);
        S[b * DM + e2 * 2 + 1] = 1.f / (sqrtf(t1) + EPSC);
    }
}

// ---------------------------------------------------------------------------
// Launch
// ---------------------------------------------------------------------------
extern "C" void kernel_launch(void* const* d_in, const int* in_sizes, int n_in,
                              void* d_out, int out_size)
{
    const float* x   = (const float*)d_in[0];
    const float* wqr = (const float*)d_in[1];
    const float* wqi = (const float*)d_in[2];
    const float* wk  = (const float*)d_in[3];
    const float* wv  = (const float*)d_in[4];
    float* out = (float*)d_out;

    uint16_t *xh, *xl, *kh, *kl, *vh, *wh, *kvh;
    float *qr, *qi, *sk, *sv;
    cudaGetSymbolAddress((void**)&xh,  g_xh);  cudaGetSymbolAddress((void**)&xl,  g_xl);
    cudaGetSymbolAddress((void**)&qr,  g_qr);  cudaGetSymbolAddress((void**)&qi,  g_qi);
    cudaGetSymbolAddress((void**)&kh,  g_kh);  cudaGetSymbolAddress((void**)&kl,  g_kl);
    cudaGetSymbolAddress((void**)&vh,  g_vh);
    cudaGetSymbolAddress((void**)&wh,  g_wh);
    cudaGetSymbolAddress((void**)&kvh, g_kvh);
    cudaGetSymbolAddress((void**)&sk,  g_sk);  cudaGetSymbolAddress((void**)&sv,  g_sv);

    cudaFuncSetAttribute(tgemm<false, 0>, cudaFuncAttributeMaxDynamicSharedMemorySize, SMEM_BYTES);
    cudaFuncSetAttribute(tgemm<false, 1>, cudaFuncAttributeMaxDynamicSharedMemorySize, SMEM_BYTES);
    cudaFuncSetAttribute(tgemm<false, 2>, cudaFuncAttributeMaxDynamicSharedMemorySize, SMEM_BYTES);
    cudaFuncSetAttribute(tgemm<true, 3>,  cudaFuncAttributeMaxDynamicSharedMemorySize, SMEM_BYTES);

    // Input conversions
    split_x<<<XELEMS / 4 / 256, 256>>>((const float4*)x, (uint2*)xh, (uint2*)xl, XELEMS / 4);
    const int wn4 = 1048576 / 4;
    cvt_h<<<wn4 / 256, 256>>>((const float4*)wqr, (uint2*)wh,             wn4);
    cvt_h<<<wn4 / 256, 256>>>((const float4*)wqi, (uint2*)(wh + 1048576), wn4);
    cvt_h<<<wn4 / 256, 256>>>((const float4*)wk,  (uint2*)(wh + 2097152), wn4);
    cvt_h<<<wn4 / 256, 256>>>((const float4*)wv,  (uint2*)(wh + 3145728), wn4);

    // Stage 1: four projections
    dim3 g1(DM / BN, (BSZ * NSEQ) / BM, 1);
    tgemm<false, 0><<<g1, 256, SMEM_BYTES>>>(xh, xl, wh,             qr, nullptr,
                                             DM, DM, DM, DM, 0, 0, 0, nullptr, nullptr);
    tgemm<false, 0><<<g1, 256, SMEM_BYTES>>>(xh, xl, wh + 1048576,   qi, nullptr,
                                             DM, DM, DM, DM, 0, 0, 0, nullptr, nullptr);
    tgemm<false, 1><<<g1, 256, SMEM_BYTES>>>(xh, xl, wh + 2097152,   kh, kl,
                                             DM, DM, DM, DM, 0, 0, 0, nullptr, nullptr);
    tgemm<false, 2><<<g1, 256, SMEM_BYTES>>>(xh, xl, wh + 3145728,   vh, nullptr,
                                             DM, DM, DM, DM, 0, 0, 0, nullptr, nullptr);

    // Stage 2: q = relu(qr)*relu(qi), split output over xh/xl (x is dead now)
    relu_prod<<<XELEMS / 4 / 256, 256>>>((const float4*)qr, (const float4*)qi,
                                         (uint2*)xh, (uint2*)xl, XELEMS / 4);

    // Stage 3: inverse L2 norms
    dim3 gs(DM / 64, BSZ);
    col_scale_sp<<<gs, 256>>>((const uint32_t*)kh, (const uint32_t*)kl, sk);
    col_scale_h<<<gs, 256>>>((const uint32_t*)vh, sv);

    // Stage 4: kv[b] = relu((K^T V) .* sk x sv), single fp16 out
    dim3 g2(DM / BN, DM / BM, BSZ);
    tgemm<true, 3><<<g2, 256, SMEM_BYTES>>>(kh, kl, vh, kvh, nullptr,
                                            NSEQ, DM, DM, DM,
                                            (long long)NSEQ * DM, (long long)NSEQ * DM,
                                            (long long)DM * DM, sk, sv);

    // Stage 5: out[b] = q[b] @ kv[b], fp32 out
    dim3 g3(DM / BN, NSEQ / BM, BSZ);
    tgemm<false, 0><<<g3, 256, SMEM_BYTES>>>(xh, xl, kvh, out, nullptr,
                                             DM, DM, DM, DM,
                                             (long long)NSEQ * DM, (long long)DM * DM,
                                             (long long)NSEQ * DM, nullptr, nullptr);
}

// round 7
// speedup vs baseline: 7.1729x; 1.7091x over previous
#include <cuda_runtime.h>
#include <cuda_fp16.h>
#include <cstdint>
#include <math.h>

#define BSZ   8
#define NSEQ  4096
#define DM    1024
#define EPSC  1e-5f

// ---------------------------------------------------------------------------
// Scratch (device globals). fp16 stored as uint16_t.
// ---------------------------------------------------------------------------
#define XELEMS (8u * 4096u * 1024u)
__device__ uint16_t g_x16[XELEMS];                 // x fp16; later reused for q fp16
__device__ float    g_qr[XELEMS];                  // stage1 qr (fp32)
__device__ float    g_qi[XELEMS];                  // stage1 qi (fp32)
__device__ uint16_t g_k16[XELEMS];                 // k fp16
__device__ uint16_t g_v16[XELEMS];                 // v fp16
__device__ uint16_t g_w16[4u * 1048576u];          // 4 weights fp16
__device__ uint16_t g_kv16[8u * 1048576u];         // kv fp16
__device__ float    g_sk[8u * 1024u], g_sv[8u * 1024u];

// ---------------------------------------------------------------------------
// Helpers
// ---------------------------------------------------------------------------
__device__ __forceinline__ uint32_t smem_u32(const void* p) {
    uint32_t a;
    asm("{ .reg .u64 t; cvta.to.shared.u64 t, %1; cvt.u32.u64 %0, t; }" : "=r"(a) : "l"(p));
    return a;
}
__device__ __forceinline__ uint32_t packh2(float x, float y) {
    __half2 h = __floats2half2_rn(x, y);
    return *reinterpret_cast<uint32_t*>(&h);
}
__device__ __forceinline__ float2 unpackh2(uint32_t u) {
    __half2 h = *reinterpret_cast<__half2*>(&u);
    return __half22float2(h);
}
__device__ __forceinline__ void ldm_x4(uint32_t* d, uint32_t a) {
    asm volatile("ldmatrix.sync.aligned.m8n8.x4.shared.b16 {%0,%1,%2,%3}, [%4];"
                 : "=r"(d[0]), "=r"(d[1]), "=r"(d[2]), "=r"(d[3]) : "r"(a));
}
__device__ __forceinline__ void ldm_x4t(uint32_t* d, uint32_t a) {
    asm volatile("ldmatrix.sync.aligned.m8n8.x4.trans.shared.b16 {%0,%1,%2,%3}, [%4];"
                 : "=r"(d[0]), "=r"(d[1]), "=r"(d[2]), "=r"(d[3]) : "r"(a));
}
__device__ __forceinline__ void mma16816(float* d, const uint32_t* a, const uint32_t* b) {
    asm volatile("mma.sync.aligned.m16n8k16.row.col.f32.f16.f16.f32 "
                 "{%0,%1,%2,%3}, {%4,%5,%6,%7}, {%8,%9}, {%0,%1,%2,%3};"
                 : "+f"(d[0]), "+f"(d[1]), "+f"(d[2]), "+f"(d[3])
                 : "r"(a[0]), "r"(a[1]), "r"(a[2]), "r"(a[3]), "r"(b[0]), "r"(b[1]));
}
__device__ __forceinline__ void cpa16(uint32_t s, const void* g) {
    asm volatile("cp.async.cg.shared.global [%0], [%1], 16;" :: "r"(s), "l"(g));
}

// ---------------------------------------------------------------------------
// Single-pass fp16 HMMA GEMM, cp.async 4-stage pipeline, one sync per iter.
// BM=BN=128, BK=32, 256 threads, warps 4m x 2n, warp tile 32x64.
// A smem (direct): [128 m][32 k], 64B rows, chunk^(m&3) swizzle
// A smem (TRA)   : [32 k][128 m], 256B rows, chunk^(k&7) swizzle
// B smem         : [32 k][128 n], 256B rows, chunk^(k&7) swizzle
// TRA=false: A gmem [M,K] (k contiguous). TRA=true: A gmem [K,M] (m contiguous).
// B gmem always [K,N] (n contiguous), fp16.
// MODE 0: fp32 C0.  MODE 2: fp16 C0.  MODE 3: scale(aux1,aux2)+relu -> fp16 C0.
// ---------------------------------------------------------------------------
#define BM  128
#define BN  128
#define BKC 32
#define STG_BYTES 16384u
#define SMEM_BYTES 65536

template <bool TRA, int MODE>
__global__ __launch_bounds__(256, 2)
void tgemm(const uint16_t* __restrict__ Ap, const uint16_t* __restrict__ Bp,
           void* __restrict__ C0,
           int K, int lda, int ldb, int ldc,
           long long sA, long long sB, long long sC,
           const float* __restrict__ aux1, const float* __restrict__ aux2)
{
    extern __shared__ char smem[];
    const uint32_t sb = smem_u32(smem);
    const int tid = threadIdx.x;
    const int wid = tid >> 5, lid = tid & 31;
    const int z = blockIdx.z;
    const int brow = blockIdx.y * BM;
    const int bcol = blockIdx.x * BN;
    const uint16_t* A_p = Ap + z * sA;
    const uint16_t* B_p = Bp + z * sB;

    const int m0 = (wid & 3) * 32;
    const int n0 = (wid >> 2) * 64;

    float acc[2][8][4];
#pragma unroll
    for (int a = 0; a < 2; ++a)
#pragma unroll
        for (int b = 0; b < 8; ++b)
#pragma unroll
            for (int d = 0; d < 4; ++d) acc[a][b][d] = 0.f;

    const int NC = K / BKC;

    auto issue = [&](int c) {
        const uint32_t st = sb + (uint32_t)(c & 3) * STG_BYTES;
        const int koff = c * BKC;
        if (TRA) {
#pragma unroll
            for (int i = 0; i < 2; ++i) {
                int idx = tid + i * 256;
                int kk = idx >> 4, cc = idx & 15;
                int g = (koff + kk) * lda + brow + cc * 8;
                uint32_t off = kk * 256 + (((uint32_t)(cc ^ (kk & 7))) << 4);
                cpa16(st + off, A_p + g);
            }
        } else {
#pragma unroll
            for (int i = 0; i < 2; ++i) {
                int idx = tid + i * 256;
                int m = idx >> 2, cc = idx & 3;
                int g = (brow + m) * lda + koff + cc * 8;
                uint32_t off = m * 64 + (((uint32_t)(cc ^ (m & 3))) << 4);
                cpa16(st + off, A_p + g);
            }
        }
#pragma unroll
        for (int i = 0; i < 2; ++i) {
            int idx = tid + i * 256;
            int kk = idx >> 4, cc = idx & 15;
            int g = (koff + kk) * ldb + bcol + cc * 8;
            uint32_t off = kk * 256 + (((uint32_t)(cc ^ (kk & 7))) << 4);
            cpa16(st + 8192 + off, B_p + g);
        }
        asm volatile("cp.async.commit_group;" ::: "memory");
    };

    auto compute = [&](int c) {
        const uint32_t st = sb + (uint32_t)(c & 3) * STG_BYTES;
#pragma unroll
        for (int ks = 0; ks < 2; ++ks) {
            uint32_t af[2][4];
#pragma unroll
            for (int mi = 0; mi < 2; ++mi) {
                if (TRA) {
                    int krow = ks * 16 + (lid & 7) + ((lid & 16) >> 1);
                    int ch = ((m0 + mi * 16) >> 3) + ((lid >> 3) & 1);
                    uint32_t off = krow * 256 + (((uint32_t)(ch ^ (krow & 7))) << 4);
                    ldm_x4t(af[mi], st + off);
                } else {
                    int row = m0 + mi * 16 + (lid & 15);
                    int ch = ks * 2 + (lid >> 4);
                    uint32_t off = row * 64 + (((uint32_t)(ch ^ (row & 3))) << 4);
                    ldm_x4(af[mi], st + off);
                }
            }
#pragma unroll
            for (int ni = 0; ni < 4; ++ni) {
                int krow = ks * 16 + (lid & 7) + (lid & 8);
                int ch = ((n0 + ni * 16) >> 3) + (lid >> 4);
                uint32_t off = krow * 256 + (((uint32_t)(ch ^ (krow & 7))) << 4) + 8192;
                uint32_t t[4];
                ldm_x4t(t, st + off);
#pragma unroll
                for (int mi = 0; mi < 2; ++mi) {
                    mma16816(acc[mi][ni * 2],     af[mi], &t[0]);
                    mma16816(acc[mi][ni * 2 + 1], af[mi], &t[2]);
                }
            }
        }
    };

    issue(0);
    issue(1);
    issue(2);
    for (int c = 0; c < NC; ++c) {
        const int pend = NC - 1 - c;
        if (pend >= 2)      asm volatile("cp.async.wait_group 2;" ::: "memory");
        else if (pend == 1) asm volatile("cp.async.wait_group 1;" ::: "memory");
        else                asm volatile("cp.async.wait_group 0;" ::: "memory");
        __syncthreads();
        if (c + 3 < NC) issue(c + 3);
        compute(c);
    }

    // ---- epilogue ----
    const int r0 = lid >> 2;
    const int c0 = (lid & 3) * 2;
#pragma unroll
    for (int mi = 0; mi < 2; ++mi) {
#pragma unroll
        for (int half = 0; half < 2; ++half) {
            const int row = brow + m0 + mi * 16 + r0 + half * 8;
            float s1 = 1.f;
            if (MODE == 3) s1 = aux1[z * DM + row];
#pragma unroll
            for (int n8 = 0; n8 < 8; ++n8) {
                float d0 = acc[mi][n8][half * 2];
                float d1 = acc[mi][n8][half * 2 + 1];
                const int col = bcol + n0 + n8 * 8 + c0;
                if (MODE == 3) {
                    d0 = fmaxf(d0 * s1 * aux2[z * DM + col], 0.f);
                    d1 = fmaxf(d1 * s1 * aux2[z * DM + col + 1], 0.f);
                }
                long long lidx = (long long)z * sC + (long long)row * ldc + col;
                if (MODE == 0) {
                    *(float2*)((float*)C0 + lidx) = make_float2(d0, d1);
                } else {
                    ((uint32_t*)C0)[lidx >> 1] = packh2(d0, d1);
                }
            }
        }
    }
}

// ---------------------------------------------------------------------------
// Elementwise kernels
// ---------------------------------------------------------------------------
// fp32 -> fp16 single
__global__ void cvt_h(const float4* __restrict__ in, uint2* __restrict__ o, int n4)
{
    int i = blockIdx.x * blockDim.x + threadIdx.x;
    if (i < n4) {
        float4 v = in[i];
        o[i] = make_uint2(packh2(v.x, v.y), packh2(v.z, v.w));
    }
}

// q = relu(qr)*relu(qi) (fp32 in), fp16 out
__global__ void relu_prod(const float4* __restrict__ ar, const float4* __restrict__ ai,
                          uint2* __restrict__ o, int n4)
{
    int i = blockIdx.x * blockDim.x + threadIdx.x;
    if (i < n4) {
        float4 r = ar[i], q = ai[i];
        float q0 = fmaxf(r.x, 0.f) * fmaxf(q.x, 0.f);
        float q1 = fmaxf(r.y, 0.f) * fmaxf(q.y, 0.f);
        float q2 = fmaxf(r.z, 0.f) * fmaxf(q.z, 0.f);
        float q3 = fmaxf(r.w, 0.f) * fmaxf(q.w, 0.f);
        o[i] = make_uint2(packh2(q0, q1), packh2(q2, q3));
    }
}

// inverse L2 norm over sequence axis from fp16
__global__ void col_scale_h(const uint32_t* __restrict__ X, float* __restrict__ S)
{
    __shared__ float red0[256], red1[256];
    const int lane = threadIdx.x & 31;
    const int sl = threadIdx.x >> 5;
    const int e2 = blockIdx.x * 32 + lane;
    const int b = blockIdx.y;
    const int base = b * (NSEQ * DM / 2) + e2;
    float s0 = 0.f, s1 = 0.f;
    for (int n = sl; n < NSEQ; n += 8) {
        float2 f = unpackh2(X[base + n * (DM / 2)]);
        s0 += f.x * f.x;
        s1 += f.y * f.y;
    }
    red0[threadIdx.x] = s0;
    red1[threadIdx.x] = s1;
    __syncthreads();
    if (sl == 0) {
        float t0 = 0.f, t1 = 0.f;
#pragma unroll
        for (int i = 0; i < 8; ++i) { t0 += red0[i * 32 + lane]; t1 += red1[i * 32 + lane]; }
        S[b * DM + e2 * 2]     = 1.f / (sqrtf(t0) + EPSC);
        S[b * DM + e2 * 2 + 1] = 1.f / (sqrtf(t1) + EPSC);
    }
}

// ---------------------------------------------------------------------------
// Launch
// ---------------------------------------------------------------------------
extern "C" void kernel_launch(void* const* d_in, const int* in_sizes, int n_in,
                              void* d_out, int out_size)
{
    const float* x   = (const float*)d_in[0];
    const float* wqr = (const float*)d_in[1];
    const float* wqi = (const float*)d_in[2];
    const float* wk  = (const float*)d_in[3];
    const float* wv  = (const float*)d_in[4];
    float* out = (float*)d_out;

    uint16_t *x16, *k16, *v16, *w16, *kv16;
    float *qr, *qi, *sk, *sv;
    cudaGetSymbolAddress((void**)&x16,  g_x16);
    cudaGetSymbolAddress((void**)&qr,   g_qr);
    cudaGetSymbolAddress((void**)&qi,   g_qi);
    cudaGetSymbolAddress((void**)&k16,  g_k16);
    cudaGetSymbolAddress((void**)&v16,  g_v16);
    cudaGetSymbolAddress((void**)&w16,  g_w16);
    cudaGetSymbolAddress((void**)&kv16, g_kv16);
    cudaGetSymbolAddress((void**)&sk,   g_sk);
    cudaGetSymbolAddress((void**)&sv,   g_sv);

    cudaFuncSetAttribute(tgemm<false, 0>, cudaFuncAttributeMaxDynamicSharedMemorySize, SMEM_BYTES);
    cudaFuncSetAttribute(tgemm<false, 2>, cudaFuncAttributeMaxDynamicSharedMemorySize, SMEM_BYTES);
    cudaFuncSetAttribute(tgemm<true, 3>,  cudaFuncAttributeMaxDynamicSharedMemorySize, SMEM_BYTES);

    // Input conversions to fp16
    cvt_h<<<XELEMS / 4 / 256, 256>>>((const float4*)x, (uint2*)x16, XELEMS / 4);
    const int wn4 = 1048576 / 4;
    cvt_h<<<wn4 / 256, 256>>>((const float4*)wqr, (uint2*)w16,             wn4);
    cvt_h<<<wn4 / 256, 256>>>((const float4*)wqi, (uint2*)(w16 + 1048576), wn4);
    cvt_h<<<wn4 / 256, 256>>>((const float4*)wk,  (uint2*)(w16 + 2097152), wn4);
    cvt_h<<<wn4 / 256, 256>>>((const float4*)wv,  (uint2*)(w16 + 3145728), wn4);

    // Stage 1: four projections
    dim3 g1(DM / BN, (BSZ * NSEQ) / BM, 1);
    tgemm<false, 0><<<g1, 256, SMEM_BYTES>>>(x16, w16,             qr,
                                             DM, DM, DM, DM, 0, 0, 0, nullptr, nullptr);
    tgemm<false, 0><<<g1, 256, SMEM_BYTES>>>(x16, w16 + 1048576,   qi,
                                             DM, DM, DM, DM, 0, 0, 0, nullptr, nullptr);
    tgemm<false, 2><<<g1, 256, SMEM_BYTES>>>(x16, w16 + 2097152,   k16,
                                             DM, DM, DM, DM, 0, 0, 0, nullptr, nullptr);
    tgemm<false, 2><<<g1, 256, SMEM_BYTES>>>(x16, w16 + 3145728,   v16,
                                             DM, DM, DM, DM, 0, 0, 0, nullptr, nullptr);

    // Stage 2: q = relu(qr)*relu(qi) -> fp16, reusing x16 (x is dead)
    relu_prod<<<XELEMS / 4 / 256, 256>>>((const float4*)qr, (const float4*)qi,
                                         (uint2*)x16, XELEMS / 4);

    // Stage 3: inverse L2 norms
    dim3 gs(DM / 64, BSZ);
    col_scale_h<<<gs, 256>>>((const uint32_t*)k16, sk);
    col_scale_h<<<gs, 256>>>((const uint32_t*)v16, sv);

    // Stage 4: kv[b] = relu((K^T V) .* sk x sv) -> fp16
    dim3 g2(DM / BN, DM / BM, BSZ);
    tgemm<true, 3><<<g2, 256, SMEM_BYTES>>>(k16, v16, kv16,
                                            NSEQ, DM, DM, DM,
                                            (long long)NSEQ * DM, (long long)NSEQ * DM,
                                            (long long)DM * DM, sk, sv);

    // Stage 5: out[b] = q[b] @ kv[b] -> fp32
    dim3 g3(DM / BN, NSEQ / BM, BSZ);
    tgemm<false, 0><<<g3, 256, SMEM_BYTES>>>(x16, kv16, out,
                                             DM, DM, DM, DM,
                                             (long long)NSEQ * DM, (long long)DM * DM,
                                             (long long)NSEQ * DM, nullptr, nullptr);
}

// round 8
// speedup vs baseline: 7.7586x; 1.0817x over previous
#include <cuda_runtime.h>
#include <cuda_fp16.h>
#include <cstdint>
#include <math.h>

#define BSZ   8
#define NSEQ  4096
#define DM    1024
#define EPSC  1e-5f

// ---------------------------------------------------------------------------
// Scratch (device globals). fp16 stored as uint16_t.
// ---------------------------------------------------------------------------
#define XELEMS (8u * 4096u * 1024u)
__device__ uint16_t g_x16[XELEMS];                 // x fp16
__device__ uint16_t g_q16[XELEMS];                 // q fp16 (gated)
__device__ uint16_t g_k16[XELEMS];                 // k fp16
__device__ uint16_t g_v16[XELEMS];                 // v fp16
__device__ uint16_t g_w16[4u * 1048576u];          // 4 weights fp16
__device__ uint16_t g_kv16[8u * 1048576u];         // kv fp16
__device__ float    g_sk[8u * 1024u], g_sv[8u * 1024u];

// ---------------------------------------------------------------------------
// Helpers
// ---------------------------------------------------------------------------
__device__ __forceinline__ uint32_t smem_u32(const void* p) {
    uint32_t a;
    asm("{ .reg .u64 t; cvta.to.shared.u64 t, %1; cvt.u32.u64 %0, t; }" : "=r"(a) : "l"(p));
    return a;
}
__device__ __forceinline__ uint32_t packh2(float x, float y) {
    __half2 h = __floats2half2_rn(x, y);
    return *reinterpret_cast<uint32_t*>(&h);
}
__device__ __forceinline__ float2 unpackh2(uint32_t u) {
    __half2 h = *reinterpret_cast<__half2*>(&u);
    return __half22float2(h);
}
__device__ __forceinline__ void ldm_x4(uint32_t* d, uint32_t a) {
    asm volatile("ldmatrix.sync.aligned.m8n8.x4.shared.b16 {%0,%1,%2,%3}, [%4];"
                 : "=r"(d[0]), "=r"(d[1]), "=r"(d[2]), "=r"(d[3]) : "r"(a));
}
__device__ __forceinline__ void ldm_x4t(uint32_t* d, uint32_t a) {
    asm volatile("ldmatrix.sync.aligned.m8n8.x4.trans.shared.b16 {%0,%1,%2,%3}, [%4];"
                 : "=r"(d[0]), "=r"(d[1]), "=r"(d[2]), "=r"(d[3]) : "r"(a));
}
__device__ __forceinline__ void mma16816(float* d, const uint32_t* a, const uint32_t* b) {
    asm volatile("mma.sync.aligned.m16n8k16.row.col.f32.f16.f16.f32 "
                 "{%0,%1,%2,%3}, {%4,%5,%6,%7}, {%8,%9}, {%0,%1,%2,%3};"
                 : "+f"(d[0]), "+f"(d[1]), "+f"(d[2]), "+f"(d[3])
                 : "r"(a[0]), "r"(a[1]), "r"(a[2]), "r"(a[3]), "r"(b[0]), "r"(b[1]));
}
__device__ __forceinline__ void cpa16(uint32_t s, const void* g) {
    asm volatile("cp.async.cg.shared.global [%0], [%1], 16;" :: "r"(s), "l"(g));
}

// ===========================================================================
// Fused dual-B GEMM (stage 1): C_o[M, 64-tile] = A @ B_o for o in {0,1},
// shared A tile. BM=128, BN=64 per output, BK=32, 256 thr, warps 4m x 2n,
// warp tile 32x32 per output.
// A smem: [128 m][32 k], 64B rows, chunk^(m&3).  B_o smem: [32 k][64 n],
// 128B rows, chunk^(k&7).
// EPI 0 (QP): C0 = fp16(relu(acc0)*relu(acc1))
// EPI 1 (KV): C0 = fp16(acc0), C1 = fp16(acc1)
// ===========================================================================
#define F_STG 16384u
#define F_SMEM 65536

template <int EPI>
__global__ __launch_bounds__(256, 2)
void tgemm2(const uint16_t* __restrict__ Ap, const uint16_t* __restrict__ B0p,
            const uint16_t* __restrict__ B1p,
            uint32_t* __restrict__ C0, uint32_t* __restrict__ C1,
            int K, int lda, int ldb, int ldc)
{
    extern __shared__ char smem[];
    const uint32_t sb = smem_u32(smem);
    const int tid = threadIdx.x;
    const int wid = tid >> 5, lid = tid & 31;
    const int brow = blockIdx.y * 128;
    const int bcol = blockIdx.x * 64;

    const int m0 = (wid & 3) * 32;
    const int n0 = (wid >> 2) * 32;

    float acc[2][2][4][4];   // [out][mi][n8][4]
#pragma unroll
    for (int o = 0; o < 2; ++o)
#pragma unroll
        for (int a = 0; a < 2; ++a)
#pragma unroll
            for (int b = 0; b < 4; ++b)
#pragma unroll
                for (int d = 0; d < 4; ++d) acc[o][a][b][d] = 0.f;

    const int NC = K / 32;

    auto issue = [&](int c) {
        const uint32_t st = sb + (uint32_t)(c & 3) * F_STG;
        const int koff = c * 32;
#pragma unroll
        for (int i = 0; i < 2; ++i) {
            int idx = tid + i * 256;
            int m = idx >> 2, cc = idx & 3;
            int g = (brow + m) * lda + koff + cc * 8;
            uint32_t off = m * 64 + (((uint32_t)(cc ^ (m & 3))) << 4);
            cpa16(st + off, Ap + g);
        }
        {
            int kk = tid >> 3, cc = tid & 7;
            int g = (koff + kk) * ldb + bcol + cc * 8;
            uint32_t off = kk * 128 + (((uint32_t)(cc ^ (kk & 7))) << 4);
            cpa16(st + 8192 + off,  B0p + g);
            cpa16(st + 12288 + off, B1p + g);
        }
        asm volatile("cp.async.commit_group;" ::: "memory");
    };

    auto compute = [&](int c) {
        const uint32_t st = sb + (uint32_t)(c & 3) * F_STG;
#pragma unroll
        for (int ks = 0; ks < 2; ++ks) {
            uint32_t af[2][4];
#pragma unroll
            for (int mi = 0; mi < 2; ++mi) {
                int row = m0 + mi * 16 + (lid & 15);
                int ch = ks * 2 + (lid >> 4);
                uint32_t off = row * 64 + (((uint32_t)(ch ^ (row & 3))) << 4);
                ldm_x4(af[mi], st + off);
            }
#pragma unroll
            for (int o = 0; o < 2; ++o) {
#pragma unroll
                for (int ni = 0; ni < 2; ++ni) {
                    int krow = ks * 16 + (lid & 7) + (lid & 8);
                    int ch = ((n0 + ni * 16) >> 3) + (lid >> 4);
                    uint32_t off = krow * 128 + (((uint32_t)(ch ^ (krow & 7))) << 4)
                                 + 8192 + (uint32_t)o * 4096;
                    uint32_t t[4];
                    ldm_x4t(t, st + off);
#pragma unroll
                    for (int mi = 0; mi < 2; ++mi) {
                        mma16816(acc[o][mi][ni * 2],     af[mi], &t[0]);
                        mma16816(acc[o][mi][ni * 2 + 1], af[mi], &t[2]);
                    }
                }
            }
        }
    };

    issue(0);
    issue(1);
    issue(2);
    for (int c = 0; c < NC; ++c) {
        const int pend = NC - 1 - c;
        if (pend >= 2)      asm volatile("cp.async.wait_group 2;" ::: "memory");
        else if (pend == 1) asm volatile("cp.async.wait_group 1;" ::: "memory");
        else                asm volatile("cp.async.wait_group 0;" ::: "memory");
        __syncthreads();
        if (c + 3 < NC) issue(c + 3);
        compute(c);
    }

    // ---- epilogue ----
    const int r0 = lid >> 2;
    const int c0 = (lid & 3) * 2;
#pragma unroll
    for (int mi = 0; mi < 2; ++mi) {
#pragma unroll
        for (int half = 0; half < 2; ++half) {
            const int row = brow + m0 + mi * 16 + r0 + half * 8;
#pragma unroll
            for (int n8 = 0; n8 < 4; ++n8) {
                const int col = bcol + n0 + n8 * 8 + c0;
                long long lidx = ((long long)row * ldc + col) >> 1;
                float a0 = acc[0][mi][n8][half * 2];
                float a1 = acc[0][mi][n8][half * 2 + 1];
                float b0 = acc[1][mi][n8][half * 2];
                float b1 = acc[1][mi][n8][half * 2 + 1];
                if (EPI == 0) {
                    float q0 = fmaxf(a0, 0.f) * fmaxf(b0, 0.f);
                    float q1 = fmaxf(a1, 0.f) * fmaxf(b1, 0.f);
                    C0[lidx] = packh2(q0, q1);
                } else {
                    C0[lidx] = packh2(a0, a1);
                    C1[lidx] = packh2(b0, b1);
                }
            }
        }
    }
}

// ===========================================================================
// Single-pass fp16 HMMA GEMM (stages 4, 5) — unchanged from R7.
// ===========================================================================
#define BM  128
#define BN  128
#define BKC 32
#define STG_BYTES 16384u
#define SMEM_BYTES 65536

template <bool TRA, int MODE>
__global__ __launch_bounds__(256, 2)
void tgemm(const uint16_t* __restrict__ Ap, const uint16_t* __restrict__ Bp,
           void* __restrict__ C0,
           int K, int lda, int ldb, int ldc,
           long long sA, long long sB, long long sC,
           const float* __restrict__ aux1, const float* __restrict__ aux2)
{
    extern __shared__ char smem[];
    const uint32_t sb = smem_u32(smem);
    const int tid = threadIdx.x;
    const int wid = tid >> 5, lid = tid & 31;
    const int z = blockIdx.z;
    const int brow = blockIdx.y * BM;
    const int bcol = blockIdx.x * BN;
    const uint16_t* A_p = Ap + z * sA;
    const uint16_t* B_p = Bp + z * sB;

    const int m0 = (wid & 3) * 32;
    const int n0 = (wid >> 2) * 64;

    float acc[2][8][4];
#pragma unroll
    for (int a = 0; a < 2; ++a)
#pragma unroll
        for (int b = 0; b < 8; ++b)
#pragma unroll
            for (int d = 0; d < 4; ++d) acc[a][b][d] = 0.f;

    const int NC = K / BKC;

    auto issue = [&](int c) {
        const uint32_t st = sb + (uint32_t)(c & 3) * STG_BYTES;
        const int koff = c * BKC;
        if (TRA) {
#pragma unroll
            for (int i = 0; i < 2; ++i) {
                int idx = tid + i * 256;
                int kk = idx >> 4, cc = idx & 15;
                int g = (koff + kk) * lda + brow + cc * 8;
                uint32_t off = kk * 256 + (((uint32_t)(cc ^ (kk & 7))) << 4);
                cpa16(st + off, A_p + g);
            }
        } else {
#pragma unroll
            for (int i = 0; i < 2; ++i) {
                int idx = tid + i * 256;
                int m = idx >> 2, cc = idx & 3;
                int g = (brow + m) * lda + koff + cc * 8;
                uint32_t off = m * 64 + (((uint32_t)(cc ^ (m & 3))) << 4);
                cpa16(st + off, A_p + g);
            }
        }
#pragma unroll
        for (int i = 0; i < 2; ++i) {
            int idx = tid + i * 256;
            int kk = idx >> 4, cc = idx & 15;
            int g = (koff + kk) * ldb + bcol + cc * 8;
            uint32_t off = kk * 256 + (((uint32_t)(cc ^ (kk & 7))) << 4);
            cpa16(st + 8192 + off, B_p + g);
        }
        asm volatile("cp.async.commit_group;" ::: "memory");
    };

    auto compute = [&](int c) {
        const uint32_t st = sb + (uint32_t)(c & 3) * STG_BYTES;
#pragma unroll
        for (int ks = 0; ks < 2; ++ks) {
            uint32_t af[2][4];
#pragma unroll
            for (int mi = 0; mi < 2; ++mi) {
                if (TRA) {
                    int krow = ks * 16 + (lid & 7) + ((lid & 16) >> 1);
                    int ch = ((m0 + mi * 16) >> 3) + ((lid >> 3) & 1);
                    uint32_t off = krow * 256 + (((uint32_t)(ch ^ (krow & 7))) << 4);
                    ldm_x4t(af[mi], st + off);
                } else {
                    int row = m0 + mi * 16 + (lid & 15);
                    int ch = ks * 2 + (lid >> 4);
                    uint32_t off = row * 64 + (((uint32_t)(ch ^ (row & 3))) << 4);
                    ldm_x4(af[mi], st + off);
                }
            }
#pragma unroll
            for (int ni = 0; ni < 4; ++ni) {
                int krow = ks * 16 + (lid & 7) + (lid & 8);
                int ch = ((n0 + ni * 16) >> 3) + (lid >> 4);
                uint32_t off = krow * 256 + (((uint32_t)(ch ^ (krow & 7))) << 4) + 8192;
                uint32_t t[4];
                ldm_x4t(t, st + off);
#pragma unroll
                for (int mi = 0; mi < 2; ++mi) {
                    mma16816(acc[mi][ni * 2],     af[mi], &t[0]);
                    mma16816(acc[mi][ni * 2 + 1], af[mi], &t[2]);
                }
            }
        }
    };

    issue(0);
    issue(1);
    issue(2);
    for (int c = 0; c < NC; ++c) {
        const int pend = NC - 1 - c;
        if (pend >= 2)      asm volatile("cp.async.wait_group 2;" ::: "memory");
        else if (pend == 1) asm volatile("cp.async.wait_group 1;" ::: "memory");
        else                asm volatile("cp.async.wait_group 0;" ::: "memory");
        __syncthreads();
        if (c + 3 < NC) issue(c + 3);
        compute(c);
    }

    // ---- epilogue ----
    const int r0 = lid >> 2;
    const int c0 = (lid & 3) * 2;
#pragma unroll
    for (int mi = 0; mi < 2; ++mi) {
#pragma unroll
        for (int half = 0; half < 2; ++half) {
            const int row = brow + m0 + mi * 16 + r0 + half * 8;
            float s1 = 1.f;
            if (MODE == 3) s1 = aux1[z * DM + row];
#pragma unroll
            for (int n8 = 0; n8 < 8; ++n8) {
                float d0 = acc[mi][n8][half * 2];
                float d1 = acc[mi][n8][half * 2 + 1];
                const int col = bcol + n0 + n8 * 8 + c0;
                if (MODE == 3) {
                    d0 = fmaxf(d0 * s1 * aux2[z * DM + col], 0.f);
                    d1 = fmaxf(d1 * s1 * aux2[z * DM + col + 1], 0.f);
                }
                long long lidx = (long long)z * sC + (long long)row * ldc + col;
                if (MODE == 0) {
                    *(float2*)((float*)C0 + lidx) = make_float2(d0, d1);
                } else {
                    ((uint32_t*)C0)[lidx >> 1] = packh2(d0, d1);
                }
            }
        }
    }
}

// ---------------------------------------------------------------------------
// Elementwise kernels
// ---------------------------------------------------------------------------
__global__ void cvt_h(const float4* __restrict__ in, uint2* __restrict__ o, int n4)
{
    int i = blockIdx.x * blockDim.x + threadIdx.x;
    if (i < n4) {
        float4 v = in[i];
        o[i] = make_uint2(packh2(v.x, v.y), packh2(v.z, v.w));
    }
}

__global__ void col_scale_h(const uint32_t* __restrict__ X, float* __restrict__ S)
{
    __shared__ float red0[256], red1[256];
    const int lane = threadIdx.x & 31;
    const int sl = threadIdx.x >> 5;
    const int e2 = blockIdx.x * 32 + lane;
    const int b = blockIdx.y;
    const int base = b * (NSEQ * DM / 2) + e2;
    float s0 = 0.f, s1 = 0.f;
    for (int n = sl; n < NSEQ; n += 8) {
        float2 f = unpackh2(X[base + n * (DM / 2)]);
        s0 += f.x * f.x;
        s1 += f.y * f.y;
    }
    red0[threadIdx.x] = s0;
    red1[threadIdx.x] = s1;
    __syncthreads();
    if (sl == 0) {
        float t0 = 0.f, t1 = 0.f;
#pragma unroll
        for (int i = 0; i < 8; ++i) { t0 += red0[i * 32 + lane]; t1 += red1[i * 32 + lane]; }
        S[b * DM + e2 * 2]     = 1.f / (sqrtf(t0) + EPSC);
        S[b * DM + e2 * 2 + 1] = 1.f / (sqrtf(t1) + EPSC);
    }
}

// ---------------------------------------------------------------------------
// Launch
// ---------------------------------------------------------------------------
extern "C" void kernel_launch(void* const* d_in, const int* in_sizes, int n_in,
                              void* d_out, int out_size)
{
    const float* x   = (const float*)d_in[0];
    const float* wqr = (const float*)d_in[1];
    const float* wqi = (const float*)d_in[2];
    const float* wk  = (const float*)d_in[3];
    const float* wv  = (const float*)d_in[4];
    float* out = (float*)d_out;

    uint16_t *x16, *q16, *k16, *v16, *w16, *kv16;
    float *sk, *sv;
    cudaGetSymbolAddress((void**)&x16,  g_x16);
    cudaGetSymbolAddress((void**)&q16,  g_q16);
    cudaGetSymbolAddress((void**)&k16,  g_k16);
    cudaGetSymbolAddress((void**)&v16,  g_v16);
    cudaGetSymbolAddress((void**)&w16,  g_w16);
    cudaGetSymbolAddress((void**)&kv16, g_kv16);
    cudaGetSymbolAddress((void**)&sk,   g_sk);
    cudaGetSymbolAddress((void**)&sv,   g_sv);

    cudaFuncSetAttribute(tgemm2<0>,       cudaFuncAttributeMaxDynamicSharedMemorySize, F_SMEM);
    cudaFuncSetAttribute(tgemm2<1>,       cudaFuncAttributeMaxDynamicSharedMemorySize, F_SMEM);
    cudaFuncSetAttribute(tgemm<false, 0>, cudaFuncAttributeMaxDynamicSharedMemorySize, SMEM_BYTES);
    cudaFuncSetAttribute(tgemm<true, 3>,  cudaFuncAttributeMaxDynamicSharedMemorySize, SMEM_BYTES);

    // Input conversions to fp16
    cvt_h<<<XELEMS / 4 / 256, 256>>>((const float4*)x, (uint2*)x16, XELEMS / 4);
    const int wn4 = 1048576 / 4;
    cvt_h<<<wn4 / 256, 256>>>((const float4*)wqr, (uint2*)w16,             wn4);
    cvt_h<<<wn4 / 256, 256>>>((const float4*)wqi, (uint2*)(w16 + 1048576), wn4);
    cvt_h<<<wn4 / 256, 256>>>((const float4*)wk,  (uint2*)(w16 + 2097152), wn4);
    cvt_h<<<wn4 / 256, 256>>>((const float4*)wv,  (uint2*)(w16 + 3145728), wn4);

    // Stage 1 fused: q (gated) and k/v in two dual-B GEMMs
    dim3 gf(DM / 64, (BSZ * NSEQ) / 128, 1);
    tgemm2<0><<<gf, 256, F_SMEM>>>(x16, w16,             w16 + 1048576,
                                   (uint32_t*)q16, nullptr, DM, DM, DM, DM);
    tgemm2<1><<<gf, 256, F_SMEM>>>(x16, w16 + 2097152,   w16 + 3145728,
                                   (uint32_t*)k16, (uint32_t*)v16, DM, DM, DM, DM);

    // Stage 3: inverse L2 norms
    dim3 gs(DM / 64, BSZ);
    col_scale_h<<<gs, 256>>>((const uint32_t*)k16, sk);
    col_scale_h<<<gs, 256>>>((const uint32_t*)v16, sv);

    // Stage 4: kv[b] = relu((K^T V) .* sk x sv) -> fp16
    dim3 g2(DM / BN, DM / BM, BSZ);
    tgemm<true, 3><<<g2, 256, SMEM_BYTES>>>(k16, v16, kv16,
                                            NSEQ, DM, DM, DM,
                                            (long long)NSEQ * DM, (long long)NSEQ * DM,
                                            (long long)DM * DM, sk, sv);

    // Stage 5: out[b] = q[b] @ kv[b] -> fp32
    dim3 g3(DM / BN, NSEQ / BM, BSZ);
    tgemm<false, 0><<<g3, 256, SMEM_BYTES>>>(q16, kv16, out,
                                             DM, DM, DM, DM,
                                             (long long)NSEQ * DM, (long long)DM * DM,
                                             (long long)NSEQ * DM, nullptr, nullptr);
}

// round 9
// speedup vs baseline: 8.5217x; 1.0984x over previous
#include <cuda_runtime.h>
#include <cuda_fp16.h>
#include <cstdint>
#include <math.h>

#define BSZ   8
#define NSEQ  4096
#define DM    1024
#define EPSC  1e-5f

// ---------------------------------------------------------------------------
// Scratch (device globals). fp16 stored as uint16_t.
// ---------------------------------------------------------------------------
#define XELEMS (8u * 4096u * 1024u)
__device__ uint16_t g_x16[XELEMS];                 // x fp16
__device__ uint16_t g_q16[XELEMS];                 // q fp16 (gated)
__device__ uint16_t g_k16[XELEMS];                 // k fp16
__device__ uint16_t g_v16[XELEMS];                 // v fp16
__device__ uint16_t g_w16[4u * 1048576u];          // 4 weights fp16
__device__ uint16_t g_kv16[8u * 1048576u];         // kv fp16
__device__ float    g_sk[8u * 1024u], g_sv[8u * 1024u];

// ---------------------------------------------------------------------------
// Helpers
// ---------------------------------------------------------------------------
__device__ __forceinline__ uint32_t smem_u32(const void* p) {
    uint32_t a;
    asm("{ .reg .u64 t; cvta.to.shared.u64 t, %1; cvt.u32.u64 %0, t; }" : "=r"(a) : "l"(p));
    return a;
}
__device__ __forceinline__ uint32_t packh2(float x, float y) {
    __half2 h = __floats2half2_rn(x, y);
    return *reinterpret_cast<uint32_t*>(&h);
}
__device__ __forceinline__ float2 unpackh2(uint32_t u) {
    __half2 h = *reinterpret_cast<__half2*>(&u);
    return __half22float2(h);
}
__device__ __forceinline__ void ldm_x4(uint32_t* d, uint32_t a) {
    asm volatile("ldmatrix.sync.aligned.m8n8.x4.shared.b16 {%0,%1,%2,%3}, [%4];"
                 : "=r"(d[0]), "=r"(d[1]), "=r"(d[2]), "=r"(d[3]) : "r"(a));
}
__device__ __forceinline__ void ldm_x4t(uint32_t* d, uint32_t a) {
    asm volatile("ldmatrix.sync.aligned.m8n8.x4.trans.shared.b16 {%0,%1,%2,%3}, [%4];"
                 : "=r"(d[0]), "=r"(d[1]), "=r"(d[2]), "=r"(d[3]) : "r"(a));
}
__device__ __forceinline__ void mma16816(float* d, const uint32_t* a, const uint32_t* b) {
    asm volatile("mma.sync.aligned.m16n8k16.row.col.f32.f16.f16.f32 "
                 "{%0,%1,%2,%3}, {%4,%5,%6,%7}, {%8,%9}, {%0,%1,%2,%3};"
                 : "+f"(d[0]), "+f"(d[1]), "+f"(d[2]), "+f"(d[3])
                 : "r"(a[0]), "r"(a[1]), "r"(a[2]), "r"(a[3]), "r"(b[0]), "r"(b[1]));
}
__device__ __forceinline__ void cpa16(uint32_t s, const void* g) {
    asm volatile("cp.async.cg.shared.global [%0], [%1], 16;" :: "r"(s), "l"(g));
}

// ===========================================================================
// Common config: BM=BN=128, BK=32, 128 threads, 4 warps (2m x 2n),
// warp tile 64x64 (single-B) / 64x(32+32) (dual-B). 4-stage cp.async.
// A smem (direct): [128 m][32 k], 64B rows, chunk^(m&3) swizzle
// A smem (TRA)   : [32 k][128 m], 256B rows, chunk^(k&7) swizzle
// B smem         : [32 k][128 n], 256B rows, chunk^(k&7) swizzle
// B_o smem (dual): [32 k][64 n], 128B rows, chunk^(k&7) swizzle
// ===========================================================================
#define STG_BYTES 16384u
#define SMEM_BYTES 65536

// ---------------------------------------------------------------------------
// Fused dual-B GEMM (stage 1). EPI 0: C0 = fp16(relu(a)*relu(b)).
// EPI 1: C0 = fp16(a), C1 = fp16(b).
// ---------------------------------------------------------------------------
template <int EPI>
__global__ __launch_bounds__(128, 2)
void tgemm2(const uint16_t* __restrict__ Ap, const uint16_t* __restrict__ B0p,
            const uint16_t* __restrict__ B1p,
            uint32_t* __restrict__ C0, uint32_t* __restrict__ C1,
            int K, int lda, int ldb, int ldc)
{
    extern __shared__ char smem[];
    const uint32_t sb = smem_u32(smem);
    const int tid = threadIdx.x;
    const int wid = tid >> 5, lid = tid & 31;
    const int brow = blockIdx.y * 128;
    const int bcol = blockIdx.x * 64;

    const int m0 = (wid & 1) * 64;
    const int n0 = (wid >> 1) * 32;

    float acc[2][4][4][4];   // [out][mi][n8][4]
#pragma unroll
    for (int o = 0; o < 2; ++o)
#pragma unroll
        for (int a = 0; a < 4; ++a)
#pragma unroll
            for (int b = 0; b < 4; ++b)
#pragma unroll
                for (int d = 0; d < 4; ++d) acc[o][a][b][d] = 0.f;

    const int NC = K / 32;

    auto issue = [&](int c) {
        const uint32_t st = sb + (uint32_t)(c & 3) * STG_BYTES;
        const int koff = c * 32;
#pragma unroll
        for (int i = 0; i < 4; ++i) {
            int idx = tid + i * 128;
            int m = idx >> 2, cc = idx & 3;
            int g = (brow + m) * lda + koff + cc * 8;
            uint32_t off = m * 64 + (((uint32_t)(cc ^ (m & 3))) << 4);
            cpa16(st + off, Ap + g);
        }
#pragma unroll
        for (int i = 0; i < 2; ++i) {
            int idx = tid + i * 128;
            int kk = idx >> 3, cc = idx & 7;
            int g = (koff + kk) * ldb + bcol + cc * 8;
            uint32_t off = kk * 128 + (((uint32_t)(cc ^ (kk & 7))) << 4);
            cpa16(st + 8192 + off,  B0p + g);
            cpa16(st + 12288 + off, B1p + g);
        }
        asm volatile("cp.async.commit_group;" ::: "memory");
    };

    auto compute = [&](int c) {
        const uint32_t st = sb + (uint32_t)(c & 3) * STG_BYTES;
#pragma unroll
        for (int ks = 0; ks < 2; ++ks) {
            uint32_t af[4][4];
#pragma unroll
            for (int mi = 0; mi < 4; ++mi) {
                int row = m0 + mi * 16 + (lid & 15);
                int ch = ks * 2 + (lid >> 4);
                uint32_t off = row * 64 + (((uint32_t)(ch ^ (row & 3))) << 4);
                ldm_x4(af[mi], st + off);
            }
#pragma unroll
            for (int o = 0; o < 2; ++o) {
#pragma unroll
                for (int ni = 0; ni < 2; ++ni) {
                    int krow = ks * 16 + (lid & 7) + (lid & 8);
                    int ch = ((n0 + ni * 16) >> 3) + (lid >> 4);
                    uint32_t off = krow * 128 + (((uint32_t)(ch ^ (krow & 7))) << 4)
                                 + 8192 + (uint32_t)o * 4096;
                    uint32_t t[4];
                    ldm_x4t(t, st + off);
#pragma unroll
                    for (int mi = 0; mi < 4; ++mi) {
                        mma16816(acc[o][mi][ni * 2],     af[mi], &t[0]);
                        mma16816(acc[o][mi][ni * 2 + 1], af[mi], &t[2]);
                    }
                }
            }
        }
    };

    issue(0);
    issue(1);
    issue(2);
    for (int c = 0; c < NC; ++c) {
        const int pend = NC - 1 - c;
        if (pend >= 2)      asm volatile("cp.async.wait_group 2;" ::: "memory");
        else if (pend == 1) asm volatile("cp.async.wait_group 1;" ::: "memory");
        else                asm volatile("cp.async.wait_group 0;" ::: "memory");
        __syncthreads();
        if (c + 3 < NC) issue(c + 3);
        compute(c);
    }

    // ---- epilogue ----
    const int r0 = lid >> 2;
    const int c0 = (lid & 3) * 2;
#pragma unroll
    for (int mi = 0; mi < 4; ++mi) {
#pragma unroll
        for (int half = 0; half < 2; ++half) {
            const int row = brow + m0 + mi * 16 + r0 + half * 8;
#pragma unroll
            for (int n8 = 0; n8 < 4; ++n8) {
                const int col = bcol + n0 + n8 * 8 + c0;
                long long lidx = ((long long)row * ldc + col) >> 1;
                float a0 = acc[0][mi][n8][half * 2];
                float a1 = acc[0][mi][n8][half * 2 + 1];
                float b0 = acc[1][mi][n8][half * 2];
                float b1 = acc[1][mi][n8][half * 2 + 1];
                if (EPI == 0) {
                    float q0 = fmaxf(a0, 0.f) * fmaxf(b0, 0.f);
                    float q1 = fmaxf(a1, 0.f) * fmaxf(b1, 0.f);
                    C0[lidx] = packh2(q0, q1);
                } else {
                    C0[lidx] = packh2(a0, a1);
                    C1[lidx] = packh2(b0, b1);
                }
            }
        }
    }
}

// ---------------------------------------------------------------------------
// Single-B GEMM (stages 4, 5). MODE 0: fp32 C0. MODE 3: scale+relu -> fp16.
// ---------------------------------------------------------------------------
template <bool TRA, int MODE>
__global__ __launch_bounds__(128, 2)
void tgemm(const uint16_t* __restrict__ Ap, const uint16_t* __restrict__ Bp,
           void* __restrict__ C0,
           int K, int lda, int ldb, int ldc,
           long long sA, long long sB, long long sC,
           const float* __restrict__ aux1, const float* __restrict__ aux2)
{
    extern __shared__ char smem[];
    const uint32_t sb = smem_u32(smem);
    const int tid = threadIdx.x;
    const int wid = tid >> 5, lid = tid & 31;
    const int z = blockIdx.z;
    const int brow = blockIdx.y * 128;
    const int bcol = blockIdx.x * 128;
    const uint16_t* A_p = Ap + z * sA;
    const uint16_t* B_p = Bp + z * sB;

    const int m0 = (wid & 1) * 64;
    const int n0 = (wid >> 1) * 64;

    float acc[4][8][4];
#pragma unroll
    for (int a = 0; a < 4; ++a)
#pragma unroll
        for (int b = 0; b < 8; ++b)
#pragma unroll
            for (int d = 0; d < 4; ++d) acc[a][b][d] = 0.f;

    const int NC = K / 32;

    auto issue = [&](int c) {
        const uint32_t st = sb + (uint32_t)(c & 3) * STG_BYTES;
        const int koff = c * 32;
        if (TRA) {
#pragma unroll
            for (int i = 0; i < 4; ++i) {
                int idx = tid + i * 128;
                int kk = idx >> 4, cc = idx & 15;
                int g = (koff + kk) * lda + brow + cc * 8;
                uint32_t off = kk * 256 + (((uint32_t)(cc ^ (kk & 7))) << 4);
                cpa16(st + off, A_p + g);
            }
        } else {
#pragma unroll
            for (int i = 0; i < 4; ++i) {
                int idx = tid + i * 128;
                int m = idx >> 2, cc = idx & 3;
                int g = (brow + m) * lda + koff + cc * 8;
                uint32_t off = m * 64 + (((uint32_t)(cc ^ (m & 3))) << 4);
                cpa16(st + off, A_p + g);
            }
        }
#pragma unroll
        for (int i = 0; i < 4; ++i) {
            int idx = tid + i * 128;
            int kk = idx >> 4, cc = idx & 15;
            int g = (koff + kk) * ldb + bcol + cc * 8;
            uint32_t off = kk * 256 + (((uint32_t)(cc ^ (kk & 7))) << 4);
            cpa16(st + 8192 + off, B_p + g);
        }
        asm volatile("cp.async.commit_group;" ::: "memory");
    };

    auto compute = [&](int c) {
        const uint32_t st = sb + (uint32_t)(c & 3) * STG_BYTES;
#pragma unroll
        for (int ks = 0; ks < 2; ++ks) {
            uint32_t af[4][4];
#pragma unroll
            for (int mi = 0; mi < 4; ++mi) {
                if (TRA) {
                    int krow = ks * 16 + (lid & 7) + ((lid & 16) >> 1);
                    int ch = ((m0 + mi * 16) >> 3) + ((lid >> 3) & 1);
                    uint32_t off = krow * 256 + (((uint32_t)(ch ^ (krow & 7))) << 4);
                    ldm_x4t(af[mi], st + off);
                } else {
                    int row = m0 + mi * 16 + (lid & 15);
                    int ch = ks * 2 + (lid >> 4);
                    uint32_t off = row * 64 + (((uint32_t)(ch ^ (row & 3))) << 4);
                    ldm_x4(af[mi], st + off);
                }
            }
#pragma unroll
            for (int ni = 0; ni < 4; ++ni) {
                int krow = ks * 16 + (lid & 7) + (lid & 8);
                int ch = ((n0 + ni * 16) >> 3) + (lid >> 4);
                uint32_t off = krow * 256 + (((uint32_t)(ch ^ (krow & 7))) << 4) + 8192;
                uint32_t t[4];
                ldm_x4t(t, st + off);
#pragma unroll
                for (int mi = 0; mi < 4; ++mi) {
                    mma16816(acc[mi][ni * 2],     af[mi], &t[0]);
                    mma16816(acc[mi][ni * 2 + 1], af[mi], &t[2]);
                }
            }
        }
    };

    issue(0);
    issue(1);
    issue(2);
    for (int c = 0; c < NC; ++c) {
        const int pend = NC - 1 - c;
        if (pend >= 2)      asm volatile("cp.async.wait_group 2;" ::: "memory");
        else if (pend == 1) asm volatile("cp.async.wait_group 1;" ::: "memory");
        else                asm volatile("cp.async.wait_group 0;" ::: "memory");
        __syncthreads();
        if (c + 3 < NC) issue(c + 3);
        compute(c);
    }

    // ---- epilogue ----
    const int r0 = lid >> 2;
    const int c0 = (lid & 3) * 2;
#pragma unroll
    for (int mi = 0; mi < 4; ++mi) {
#pragma unroll
        for (int half = 0; half < 2; ++half) {
            const int row = brow + m0 + mi * 16 + r0 + half * 8;
            float s1 = 1.f;
            if (MODE == 3) s1 = aux1[z * DM + row];
#pragma unroll
            for (int n8 = 0; n8 < 8; ++n8) {
                float d0 = acc[mi][n8][half * 2];
                float d1 = acc[mi][n8][half * 2 + 1];
                const int col = bcol + n0 + n8 * 8 + c0;
                if (MODE == 3) {
                    d0 = fmaxf(d0 * s1 * aux2[z * DM + col], 0.f);
                    d1 = fmaxf(d1 * s1 * aux2[z * DM + col + 1], 0.f);
                }
                long long lidx = (long long)z * sC + (long long)row * ldc + col;
                if (MODE == 0) {
                    *(float2*)((float*)C0 + lidx) = make_float2(d0, d1);
                } else {
                    ((uint32_t*)C0)[lidx >> 1] = packh2(d0, d1);
                }
            }
        }
    }
}

// ---------------------------------------------------------------------------
// Elementwise kernels
// ---------------------------------------------------------------------------
__global__ void cvt_h(const float4* __restrict__ in, uint2* __restrict__ o, int n4)
{
    int i = blockIdx.x * blockDim.x + threadIdx.x;
    if (i < n4) {
        float4 v = in[i];
        o[i] = make_uint2(packh2(v.x, v.y), packh2(v.z, v.w));
    }
}

__global__ void col_scale_h(const uint32_t* __restrict__ X, float* __restrict__ S)
{
    __shared__ float red0[256], red1[256];
    const int lane = threadIdx.x & 31;
    const int sl = threadIdx.x >> 5;
    const int e2 = blockIdx.x * 32 + lane;
    const int b = blockIdx.y;
    const int base = b * (NSEQ * DM / 2) + e2;
    float s0 = 0.f, s1 = 0.f;
    for (int n = sl; n < NSEQ; n += 8) {
        float2 f = unpackh2(X[base + n * (DM / 2)]);
        s0 += f.x * f.x;
        s1 += f.y * f.y;
    }
    red0[threadIdx.x] = s0;
    red1[threadIdx.x] = s1;
    __syncthreads();
    if (sl == 0) {
        float t0 = 0.f, t1 = 0.f;
#pragma unroll
        for (int i = 0; i < 8; ++i) { t0 += red0[i * 32 + lane]; t1 += red1[i * 32 + lane]; }
        S[b * DM + e2 * 2]     = 1.f / (sqrtf(t0) + EPSC);
        S[b * DM + e2 * 2 + 1] = 1.f / (sqrtf(t1) + EPSC);
    }
}

// ---------------------------------------------------------------------------
// Launch
// ---------------------------------------------------------------------------
extern "C" void kernel_launch(void* const* d_in, const int* in_sizes, int n_in,
                              void* d_out, int out_size)
{
    const float* x   = (const float*)d_in[0];
    const float* wqr = (const float*)d_in[1];
    const float* wqi = (const float*)d_in[2];
    const float* wk  = (const float*)d_in[3];
    const float* wv  = (const float*)d_in[4];
    float* out = (float*)d_out;

    uint16_t *x16, *q16, *k16, *v16, *w16, *kv16;
    float *sk, *sv;
    cudaGetSymbolAddress((void**)&x16,  g_x16);
    cudaGetSymbolAddress((void**)&q16,  g_q16);
    cudaGetSymbolAddress((void**)&k16,  g_k16);
    cudaGetSymbolAddress((void**)&v16,  g_v16);
    cudaGetSymbolAddress((void**)&w16,  g_w16);
    cudaGetSymbolAddress((void**)&kv16, g_kv16);
    cudaGetSymbolAddress((void**)&sk,   g_sk);
    cudaGetSymbolAddress((void**)&sv,   g_sv);

    cudaFuncSetAttribute(tgemm2<0>,       cudaFuncAttributeMaxDynamicSharedMemorySize, SMEM_BYTES);
    cudaFuncSetAttribute(tgemm2<1>,       cudaFuncAttributeMaxDynamicSharedMemorySize, SMEM_BYTES);
    cudaFuncSetAttribute(tgemm<false, 0>, cudaFuncAttributeMaxDynamicSharedMemorySize, SMEM_BYTES);
    cudaFuncSetAttribute(tgemm<true, 3>,  cudaFuncAttributeMaxDynamicSharedMemorySize, SMEM_BYTES);

    // Input conversions to fp16
    cvt_h<<<XELEMS / 4 / 256, 256>>>((const float4*)x, (uint2*)x16, XELEMS / 4);
    const int wn4 = 1048576 / 4;
    cvt_h<<<wn4 / 256, 256>>>((const float4*)wqr, (uint2*)w16,             wn4);
    cvt_h<<<wn4 / 256, 256>>>((const float4*)wqi, (uint2*)(w16 + 1048576), wn4);
    cvt_h<<<wn4 / 256, 256>>>((const float4*)wk,  (uint2*)(w16 + 2097152), wn4);
    cvt_h<<<wn4 / 256, 256>>>((const float4*)wv,  (uint2*)(w16 + 3145728), wn4);

    // Stage 1 fused: q (gated) and k/v in two dual-B GEMMs
    dim3 gf(DM / 64, (BSZ * NSEQ) / 128, 1);
    tgemm2<0><<<gf, 128, SMEM_BYTES>>>(x16, w16,             w16 + 1048576,
                                       (uint32_t*)q16, nullptr, DM, DM, DM, DM);
    tgemm2<1><<<gf, 128, SMEM_BYTES>>>(x16, w16 + 2097152,   w16 + 3145728,
                                       (uint32_t*)k16, (uint32_t*)v16, DM, DM, DM, DM);

    // Stage 3: inverse L2 norms
    dim3 gs(DM / 64, BSZ);
    col_scale_h<<<gs, 256>>>((const uint32_t*)k16, sk);
    col_scale_h<<<gs, 256>>>((const uint32_t*)v16, sv);

    // Stage 4: kv[b] = relu((K^T V) .* sk x sv) -> fp16
    dim3 g2(DM / 128, DM / 128, BSZ);
    tgemm<true, 3><<<g2, 128, SMEM_BYTES>>>(k16, v16, kv16,
                                            NSEQ, DM, DM, DM,
                                            (long long)NSEQ * DM, (long long)NSEQ * DM,
                                            (long long)DM * DM, sk, sv);

    // Stage 5: out[b] = q[b] @ kv[b] -> fp32
    dim3 g3(DM / 128, NSEQ / 128, BSZ);
    tgemm<false, 0><<<g3, 128, SMEM_BYTES>>>(q16, kv16, out,
                                             DM, DM, DM, DM,
                                             (long long)NSEQ * DM, (long long)DM * DM,
                                             (long long)NSEQ * DM, nullptr, nullptr);
}

// round 10
// speedup vs baseline: 9.0982x; 1.0676x over previous
#include <cuda_runtime.h>
#include <cuda_fp16.h>
#include <cstdint>
#include <math.h>

#define BSZ   8
#define NSEQ  4096
#define DM    1024
#define EPSC  1e-5f

// ---------------------------------------------------------------------------
// Scratch (device globals). fp16 stored as uint16_t.
// ---------------------------------------------------------------------------
#define XELEMS (8u * 4096u * 1024u)
__device__ uint16_t g_x16[XELEMS];                 // x fp16
__device__ uint16_t g_q16[XELEMS];                 // q fp16 (gated)
__device__ uint16_t g_k16[XELEMS];                 // k fp16
__device__ uint16_t g_v16[XELEMS];                 // v fp16
__device__ uint16_t g_w16[4u * 1048576u];          // 4 weights fp16
__device__ uint16_t g_kv16[8u * 1048576u];         // kv fp16
__device__ float    g_sk[8u * 1024u], g_sv[8u * 1024u];

// ---------------------------------------------------------------------------
// Helpers
// ---------------------------------------------------------------------------
__device__ __forceinline__ uint32_t smem_u32(const void* p) {
    uint32_t a;
    asm("{ .reg .u64 t; cvta.to.shared.u64 t, %1; cvt.u32.u64 %0, t; }" : "=r"(a) : "l"(p));
    return a;
}
__device__ __forceinline__ uint32_t packh2(float x, float y) {
    __half2 h = __floats2half2_rn(x, y);
    return *reinterpret_cast<uint32_t*>(&h);
}
__device__ __forceinline__ float2 unpackh2(uint32_t u) {
    __half2 h = *reinterpret_cast<__half2*>(&u);
    return __half22float2(h);
}
__device__ __forceinline__ void ldm_x4(uint32_t* d, uint32_t a) {
    asm volatile("ldmatrix.sync.aligned.m8n8.x4.shared.b16 {%0,%1,%2,%3}, [%4];"
                 : "=r"(d[0]), "=r"(d[1]), "=r"(d[2]), "=r"(d[3]) : "r"(a));
}
__device__ __forceinline__ void ldm_x4t(uint32_t* d, uint32_t a) {
    asm volatile("ldmatrix.sync.aligned.m8n8.x4.trans.shared.b16 {%0,%1,%2,%3}, [%4];"
                 : "=r"(d[0]), "=r"(d[1]), "=r"(d[2]), "=r"(d[3]) : "r"(a));
}
__device__ __forceinline__ void mma16816(float* d, const uint32_t* a, const uint32_t* b) {
    asm volatile("mma.sync.aligned.m16n8k16.row.col.f32.f16.f16.f32 "
                 "{%0,%1,%2,%3}, {%4,%5,%6,%7}, {%8,%9}, {%0,%1,%2,%3};"
                 : "+f"(d[0]), "+f"(d[1]), "+f"(d[2]), "+f"(d[3])
                 : "r"(a[0]), "r"(a[1]), "r"(a[2]), "r"(a[3]), "r"(b[0]), "r"(b[1]));
}
__device__ __forceinline__ void cpa16(uint32_t s, const void* g) {
    asm volatile("cp.async.cg.shared.global [%0], [%1], 16;" :: "r"(s), "l"(g));
}

// ===========================================================================
// Common config: BM=BN=128, BK=64, 128 threads, 4 warps, warp tile 64x64
// (single-B) / 64x(32+32) (dual-B). 3-stage cp.async, one sync per BK=64.
// A smem (direct): [128 m][64 k], 128B rows, chunk^(m&7) swizzle  (16 KB)
// A smem (TRA)   : [64 k][128 m], 256B rows, chunk^(k&7) swizzle  (16 KB)
// B smem         : [64 k][128 n], 256B rows, chunk^(k&7) swizzle  (16 KB)
// B_o smem (dual): [64 k][64 n],  128B rows, chunk^(k&7) swizzle  (8 KB x2)
// ===========================================================================
#define STG_BYTES 32768u
#define SMEM_BYTES 98304

// ---------------------------------------------------------------------------
// Fused dual-B GEMM (stage 1). EPI 0: C0 = fp16(relu(a)*relu(b)).
// EPI 1: C0 = fp16(a), C1 = fp16(b).
// ---------------------------------------------------------------------------
template <int EPI>
__global__ __launch_bounds__(128, 2)
void tgemm2(const uint16_t* __restrict__ Ap, const uint16_t* __restrict__ B0p,
            const uint16_t* __restrict__ B1p,
            uint32_t* __restrict__ C0, uint32_t* __restrict__ C1,
            int K, int lda, int ldb, int ldc)
{
    extern __shared__ char smem[];
    const uint32_t sb = smem_u32(smem);
    const int tid = threadIdx.x;
    const int wid = tid >> 5, lid = tid & 31;
    const int brow = blockIdx.y * 128;
    const int bcol = blockIdx.x * 64;

    const int m0 = (wid & 1) * 64;
    const int n0 = (wid >> 1) * 32;

    float acc[2][4][4][4];   // [out][mi][n8][4]
#pragma unroll
    for (int o = 0; o < 2; ++o)
#pragma unroll
        for (int a = 0; a < 4; ++a)
#pragma unroll
            for (int b = 0; b < 4; ++b)
#pragma unroll
                for (int d = 0; d < 4; ++d) acc[o][a][b][d] = 0.f;

    const int NC = K / 64;

    auto issue = [&](int c) {
        const uint32_t st = sb + (uint32_t)(c % 3) * STG_BYTES;
        const int koff = c * 64;
        // A: [128 m][64 k] fp16, 128B rows
#pragma unroll
        for (int i = 0; i < 8; ++i) {
            int idx = tid + i * 128;
            int m = idx >> 3, cc = idx & 7;
            int g = (brow + m) * lda + koff + cc * 8;
            uint32_t off = m * 128 + (((uint32_t)(cc ^ (m & 7))) << 4);
            cpa16(st + off, Ap + g);
        }
        // B0/B1: [64 k][64 n] fp16, 128B rows
#pragma unroll
        for (int i = 0; i < 4; ++i) {
            int idx = tid + i * 128;
            int kk = idx >> 3, cc = idx & 7;
            int g = (koff + kk) * ldb + bcol + cc * 8;
            uint32_t off = kk * 128 + (((uint32_t)(cc ^ (kk & 7))) << 4);
            cpa16(st + 16384 + off, B0p + g);
            cpa16(st + 24576 + off, B1p + g);
        }
        asm volatile("cp.async.commit_group;" ::: "memory");
    };

    auto compute = [&](int c) {
        const uint32_t st = sb + (uint32_t)(c % 3) * STG_BYTES;
#pragma unroll
        for (int ks = 0; ks < 4; ++ks) {
            uint32_t af[4][4];
#pragma unroll
            for (int mi = 0; mi < 4; ++mi) {
                int row = m0 + mi * 16 + (lid & 15);
                int ch = ks * 2 + (lid >> 4);
                uint32_t off = row * 128 + (((uint32_t)(ch ^ (row & 7))) << 4);
                ldm_x4(af[mi], st + off);
            }
#pragma unroll
            for (int o = 0; o < 2; ++o) {
#pragma unroll
                for (int ni = 0; ni < 2; ++ni) {
                    int krow = ks * 16 + (lid & 7) + (lid & 8);
                    int ch = ((n0 + ni * 16) >> 3) + (lid >> 4);
                    uint32_t off = krow * 128 + (((uint32_t)(ch ^ (krow & 7))) << 4)
                                 + 16384 + (uint32_t)o * 8192;
                    uint32_t t[4];
                    ldm_x4t(t, st + off);
#pragma unroll
                    for (int mi = 0; mi < 4; ++mi) {
                        mma16816(acc[o][mi][ni * 2],     af[mi], &t[0]);
                        mma16816(acc[o][mi][ni * 2 + 1], af[mi], &t[2]);
                    }
                }
            }
        }
    };

    issue(0);
    issue(1);
    for (int c = 0; c < NC; ++c) {
        if (c + 1 < NC) asm volatile("cp.async.wait_group 1;" ::: "memory");
        else            asm volatile("cp.async.wait_group 0;" ::: "memory");
        __syncthreads();
        if (c + 2 < NC) issue(c + 2);
        compute(c);
    }

    // ---- epilogue ----
    const int r0 = lid >> 2;
    const int c0 = (lid & 3) * 2;
#pragma unroll
    for (int mi = 0; mi < 4; ++mi) {
#pragma unroll
        for (int half = 0; half < 2; ++half) {
            const int row = brow + m0 + mi * 16 + r0 + half * 8;
#pragma unroll
            for (int n8 = 0; n8 < 4; ++n8) {
                const int col = bcol + n0 + n8 * 8 + c0;
                long long lidx = ((long long)row * ldc + col) >> 1;
                float a0 = acc[0][mi][n8][half * 2];
                float a1 = acc[0][mi][n8][half * 2 + 1];
                float b0 = acc[1][mi][n8][half * 2];
                float b1 = acc[1][mi][n8][half * 2 + 1];
                if (EPI == 0) {
                    float q0 = fmaxf(a0, 0.f) * fmaxf(b0, 0.f);
                    float q1 = fmaxf(a1, 0.f) * fmaxf(b1, 0.f);
                    C0[lidx] = packh2(q0, q1);
                } else {
                    C0[lidx] = packh2(a0, a1);
                    C1[lidx] = packh2(b0, b1);
                }
            }
        }
    }
}

// ---------------------------------------------------------------------------
// Single-B GEMM (stages 4, 5). MODE 0: fp32 C0. MODE 3: scale+relu -> fp16.
// ---------------------------------------------------------------------------
template <bool TRA, int MODE>
__global__ __launch_bounds__(128, 2)
void tgemm(const uint16_t* __restrict__ Ap, const uint16_t* __restrict__ Bp,
           void* __restrict__ C0,
           int K, int lda, int ldb, int ldc,
           long long sA, long long sB, long long sC,
           const float* __restrict__ aux1, const float* __restrict__ aux2)
{
    extern __shared__ char smem[];
    const uint32_t sb = smem_u32(smem);
    const int tid = threadIdx.x;
    const int wid = tid >> 5, lid = tid & 31;
    const int z = blockIdx.z;
    const int brow = blockIdx.y * 128;
    const int bcol = blockIdx.x * 128;
    const uint16_t* A_p = Ap + z * sA;
    const uint16_t* B_p = Bp + z * sB;

    const int m0 = (wid & 1) * 64;
    const int n0 = (wid >> 1) * 64;

    float acc[4][8][4];
#pragma unroll
    for (int a = 0; a < 4; ++a)
#pragma unroll
        for (int b = 0; b < 8; ++b)
#pragma unroll
            for (int d = 0; d < 4; ++d) acc[a][b][d] = 0.f;

    const int NC = K / 64;

    auto issue = [&](int c) {
        const uint32_t st = sb + (uint32_t)(c % 3) * STG_BYTES;
        const int koff = c * 64;
        if (TRA) {
            // A: [64 k][128 m], 256B rows
#pragma unroll
            for (int i = 0; i < 8; ++i) {
                int idx = tid + i * 128;
                int kk = idx >> 4, cc = idx & 15;
                int g = (koff + kk) * lda + brow + cc * 8;
                uint32_t off = kk * 256 + (((uint32_t)(cc ^ (kk & 7))) << 4);
                cpa16(st + off, A_p + g);
            }
        } else {
            // A: [128 m][64 k], 128B rows
#pragma unroll
            for (int i = 0; i < 8; ++i) {
                int idx = tid + i * 128;
                int m = idx >> 3, cc = idx & 7;
                int g = (brow + m) * lda + koff + cc * 8;
                uint32_t off = m * 128 + (((uint32_t)(cc ^ (m & 7))) << 4);
                cpa16(st + off, A_p + g);
            }
        }
        // B: [64 k][128 n], 256B rows
#pragma unroll
        for (int i = 0; i < 8; ++i) {
            int idx = tid + i * 128;
            int kk = idx >> 4, cc = idx & 15;
            int g = (koff + kk) * ldb + bcol + cc * 8;
            uint32_t off = kk * 256 + (((uint32_t)(cc ^ (kk & 7))) << 4);
            cpa16(st + 16384 + off, B_p + g);
        }
        asm volatile("cp.async.commit_group;" ::: "memory");
    };

    auto compute = [&](int c) {
        const uint32_t st = sb + (uint32_t)(c % 3) * STG_BYTES;
#pragma unroll
        for (int ks = 0; ks < 4; ++ks) {
            uint32_t af[4][4];
#pragma unroll
            for (int mi = 0; mi < 4; ++mi) {
                if (TRA) {
                    int krow = ks * 16 + (lid & 7) + ((lid & 16) >> 1);
                    int ch = ((m0 + mi * 16) >> 3) + ((lid >> 3) & 1);
                    uint32_t off = krow * 256 + (((uint32_t)(ch ^ (krow & 7))) << 4);
                    ldm_x4t(af[mi], st + off);
                } else {
                    int row = m0 + mi * 16 + (lid & 15);
                    int ch = ks * 2 + (lid >> 4);
                    uint32_t off = row * 128 + (((uint32_t)(ch ^ (row & 7))) << 4);
                    ldm_x4(af[mi], st + off);
                }
            }
#pragma unroll
            for (int ni = 0; ni < 4; ++ni) {
                int krow = ks * 16 + (lid & 7) + (lid & 8);
                int ch = ((n0 + ni * 16) >> 3) + (lid >> 4);
                uint32_t off = krow * 256 + (((uint32_t)(ch ^ (krow & 7))) << 4) + 16384;
                uint32_t t[4];
                ldm_x4t(t, st + off);
#pragma unroll
                for (int mi = 0; mi < 4; ++mi) {
                    mma16816(acc[mi][ni * 2],     af[mi], &t[0]);
                    mma16816(acc[mi][ni * 2 + 1], af[mi], &t[2]);
                }
            }
        }
    };

    issue(0);
    issue(1);
    for (int c = 0; c < NC; ++c) {
        if (c + 1 < NC) asm volatile("cp.async.wait_group 1;" ::: "memory");
        else            asm volatile("cp.async.wait_group 0;" ::: "memory");
        __syncthreads();
        if (c + 2 < NC) issue(c + 2);
        compute(c);
    }

    // ---- epilogue ----
    const int r0 = lid >> 2;
    const int c0 = (lid & 3) * 2;
#pragma unroll
    for (int mi = 0; mi < 4; ++mi) {
#pragma unroll
        for (int half = 0; half < 2; ++half) {
            const int row = brow + m0 + mi * 16 + r0 + half * 8;
            float s1 = 1.f;
            if (MODE == 3) s1 = aux1[z * DM + row];
#pragma unroll
            for (int n8 = 0; n8 < 8; ++n8) {
                float d0 = acc[mi][n8][half * 2];
                float d1 = acc[mi][n8][half * 2 + 1];
                const int col = bcol + n0 + n8 * 8 + c0;
                if (MODE == 3) {
                    d0 = fmaxf(d0 * s1 * aux2[z * DM + col], 0.f);
                    d1 = fmaxf(d1 * s1 * aux2[z * DM + col + 1], 0.f);
                }
                long long lidx = (long long)z * sC + (long long)row * ldc + col;
                if (MODE == 0) {
                    *(float2*)((float*)C0 + lidx) = make_float2(d0, d1);
                } else {
                    ((uint32_t*)C0)[lidx >> 1] = packh2(d0, d1);
                }
            }
        }
    }
}

// ---------------------------------------------------------------------------
// Elementwise kernels
// ---------------------------------------------------------------------------
__global__ void cvt_h(const float4* __restrict__ in, uint2* __restrict__ o, int n4)
{
    int i = blockIdx.x * blockDim.x + threadIdx.x;
    if (i < n4) {
        float4 v = in[i];
        o[i] = make_uint2(packh2(v.x, v.y), packh2(v.z, v.w));
    }
}

// dual-input inverse L2 norm over sequence axis from fp16
__global__ void col_scale2_h(const uint32_t* __restrict__ X0, const uint32_t* __restrict__ X1,
                             float* __restrict__ S0, float* __restrict__ S1)
{
    __shared__ float red0[256], red1[256];
    const uint32_t* X = blockIdx.z ? X1 : X0;
    float* S = blockIdx.z ? S1 : S0;
    const int lane = threadIdx.x & 31;
    const int sl = threadIdx.x >> 5;
    const int e2 = blockIdx.x * 32 + lane;
    const int b = blockIdx.y;
    const int base = b * (NSEQ * DM / 2) + e2;
    float s0 = 0.f, s1 = 0.f;
    for (int n = sl; n < NSEQ; n += 8) {
        float2 f = unpackh2(X[base + n * (DM / 2)]);
        s0 += f.x * f.x;
        s1 += f.y * f.y;
    }
    red0[threadIdx.x] = s0;
    red1[threadIdx.x] = s1;
    __syncthreads();
    if (sl == 0) {
        float t0 = 0.f, t1 = 0.f;
#pragma unroll
        for (int i = 0; i < 8; ++i) { t0 += red0[i * 32 + lane]; t1 += red1[i * 32 + lane]; }
        S[b * DM + e2 * 2]     = 1.f / (sqrtf(t0) + EPSC);
        S[b * DM + e2 * 2 + 1] = 1.f / (sqrtf(t1) + EPSC);
    }
}

// ---------------------------------------------------------------------------
// Launch
// ---------------------------------------------------------------------------
extern "C" void kernel_launch(void* const* d_in, const int* in_sizes, int n_in,
                              void* d_out, int out_size)
{
    const float* x   = (const float*)d_in[0];
    const float* wqr = (const float*)d_in[1];
    const float* wqi = (const float*)d_in[2];
    const float* wk  = (const float*)d_in[3];
    const float* wv  = (const float*)d_in[4];
    float* out = (float*)d_out;

    uint16_t *x16, *q16, *k16, *v16, *w16, *kv16;
    float *sk, *sv;
    cudaGetSymbolAddress((void**)&x16,  g_x16);
    cudaGetSymbolAddress((void**)&q16,  g_q16);
    cudaGetSymbolAddress((void**)&k16,  g_k16);
    cudaGetSymbolAddress((void**)&v16,  g_v16);
    cudaGetSymbolAddress((void**)&w16,  g_w16);
    cudaGetSymbolAddress((void**)&kv16, g_kv16);
    cudaGetSymbolAddress((void**)&sk,   g_sk);
    cudaGetSymbolAddress((void**)&sv,   g_sv);

    cudaFuncSetAttribute(tgemm2<0>,       cudaFuncAttributeMaxDynamicSharedMemorySize, SMEM_BYTES);
    cudaFuncSetAttribute(tgemm2<1>,       cudaFuncAttributeMaxDynamicSharedMemorySize, SMEM_BYTES);
    cudaFuncSetAttribute(tgemm<false, 0>, cudaFuncAttributeMaxDynamicSharedMemorySize, SMEM_BYTES);
    cudaFuncSetAttribute(tgemm<true, 3>,  cudaFuncAttributeMaxDynamicSharedMemorySize, SMEM_BYTES);

    // Input conversions to fp16
    cvt_h<<<XELEMS / 4 / 256, 256>>>((const float4*)x, (uint2*)x16, XELEMS / 4);
    const int wn4 = 1048576 / 4;
    cvt_h<<<wn4 / 256, 256>>>((const float4*)wqr, (uint2*)w16,             wn4);
    cvt_h<<<wn4 / 256, 256>>>((const float4*)wqi, (uint2*)(w16 + 1048576), wn4);
    cvt_h<<<wn4 / 256, 256>>>((const float4*)wk,  (uint2*)(w16 + 2097152), wn4);
    cvt_h<<<wn4 / 256, 256>>>((const float4*)wv,  (uint2*)(w16 + 3145728), wn4);

    // Stage 1 fused: q (gated) and k/v in two dual-B GEMMs
    dim3 gf(DM / 64, (BSZ * NSEQ) / 128, 1);
    tgemm2<0><<<gf, 128, SMEM_BYTES>>>(x16, w16,             w16 + 1048576,
                                       (uint32_t*)q16, nullptr, DM, DM, DM, DM);
    tgemm2<1><<<gf, 128, SMEM_BYTES>>>(x16, w16 + 2097152,   w16 + 3145728,
                                       (uint32_t*)k16, (uint32_t*)v16, DM, DM, DM, DM);

    // Stage 3: inverse L2 norms (k and v in one launch)
    dim3 gs(DM / 64, BSZ, 2);
    col_scale2_h<<<gs, 256>>>((const uint32_t*)k16, (const uint32_t*)v16, sk, sv);

    // Stage 4: kv[b] = relu((K^T V) .* sk x sv) -> fp16
    dim3 g2(DM / 128, DM / 128, BSZ);
    tgemm<true, 3><<<g2, 128, SMEM_BYTES>>>(k16, v16, kv16,
                                            NSEQ, DM, DM, DM,
                                            (long long)NSEQ * DM, (long long)NSEQ * DM,
                                            (long long)DM * DM, sk, sv);

    // Stage 5: out[b] = q[b] @ kv[b] -> fp32
    dim3 g3(DM / 128, NSEQ / 128, BSZ);
    tgemm<false, 0><<<g3, 128, SMEM_BYTES>>>(q16, kv16, out,
                                             DM, DM, DM, DM,
                                             (long long)NSEQ * DM, (long long)DM * DM,
                                             (long long)NSEQ * DM, nullptr, nullptr);
}

// round 11
// speedup vs baseline: 9.1186x; 1.0022x over previous
#include <cuda_runtime.h>
#include <cuda_fp16.h>
#include <cstdint>
#include <math.h>

#define BSZ   8
#define NSEQ  4096
#define DM    1024
#define EPSC  1e-5f

// ---------------------------------------------------------------------------
// Scratch (device globals). fp16 stored as uint16_t.
// ---------------------------------------------------------------------------
#define XELEMS (8u * 4096u * 1024u)
__device__ uint16_t g_x16[XELEMS];                 // x fp16
__device__ uint16_t g_q16[XELEMS];                 // q fp16 (gated)
__device__ uint16_t g_k16[XELEMS];                 // k fp16
__device__ uint16_t g_v16[XELEMS];                 // v fp16
__device__ uint16_t g_w16[4u * 1048576u];          // 4 weights fp16
__device__ uint16_t g_kv16[8u * 1048576u];         // kv fp16
__device__ float    g_sk[8u * 1024u], g_sv[8u * 1024u];

// ---------------------------------------------------------------------------
// Helpers
// ---------------------------------------------------------------------------
__device__ __forceinline__ uint32_t smem_u32(const void* p) {
    uint32_t a;
    asm("{ .reg .u64 t; cvta.to.shared.u64 t, %1; cvt.u32.u64 %0, t; }" : "=r"(a) : "l"(p));
    return a;
}
__device__ __forceinline__ uint32_t packh2(float x, float y) {
    __half2 h = __floats2half2_rn(x, y);
    return *reinterpret_cast<uint32_t*>(&h);
}
__device__ __forceinline__ float2 unpackh2(uint32_t u) {
    __half2 h = *reinterpret_cast<__half2*>(&u);
    return __half22float2(h);
}
__device__ __forceinline__ void ldm_x4(uint32_t* d, uint32_t a) {
    asm volatile("ldmatrix.sync.aligned.m8n8.x4.shared.b16 {%0,%1,%2,%3}, [%4];"
                 : "=r"(d[0]), "=r"(d[1]), "=r"(d[2]), "=r"(d[3]) : "r"(a));
}
__device__ __forceinline__ void ldm_x4t(uint32_t* d, uint32_t a) {
    asm volatile("ldmatrix.sync.aligned.m8n8.x4.trans.shared.b16 {%0,%1,%2,%3}, [%4];"
                 : "=r"(d[0]), "=r"(d[1]), "=r"(d[2]), "=r"(d[3]) : "r"(a));
}
__device__ __forceinline__ void mma16816(float* d, const uint32_t* a, const uint32_t* b) {
    asm volatile("mma.sync.aligned.m16n8k16.row.col.f32.f16.f16.f32 "
                 "{%0,%1,%2,%3}, {%4,%5,%6,%7}, {%8,%9}, {%0,%1,%2,%3};"
                 : "+f"(d[0]), "+f"(d[1]), "+f"(d[2]), "+f"(d[3])
                 : "r"(a[0]), "r"(a[1]), "r"(a[2]), "r"(a[3]), "r"(b[0]), "r"(b[1]));
}
__device__ __forceinline__ void cpa16(uint32_t s, const void* g) {
    asm volatile("cp.async.cg.shared.global [%0], [%1], 16;" :: "r"(s), "l"(g));
}

// ===========================================================================
// Common config: BM=BN=128, BK=64, 128 threads, 4 warps, warp tile 64x64
// (single-B) / 64x(32+32) (dual-B). 3-stage cp.async, one sync per BK=64.
// A smem (direct): [128 m][64 k], 128B rows, chunk^(m&7) swizzle  (16 KB)
// A smem (TRA)   : [64 k][128 m], 256B rows, chunk^(k&7) swizzle  (16 KB)
// B smem         : [64 k][128 n], 256B rows, chunk^(k&7) swizzle  (16 KB)
// B_o smem (dual): [64 k][64 n],  128B rows, chunk^(k&7) swizzle  (8 KB x2)
// ===========================================================================
#define STG_BYTES 32768u
#define SMEM_BYTES 98304

// ---------------------------------------------------------------------------
// Fused dual-B GEMM (stage 1). EPI 0: C0 = fp16(relu(a)*relu(b)).
// EPI 1: C0 = fp16(a), C1 = fp16(b).
// ---------------------------------------------------------------------------
template <int EPI>
__global__ __launch_bounds__(128, 2)
void tgemm2(const uint16_t* __restrict__ Ap, const uint16_t* __restrict__ B0p,
            const uint16_t* __restrict__ B1p,
            uint32_t* __restrict__ C0, uint32_t* __restrict__ C1,
            int K, int lda, int ldb, int ldc)
{
    extern __shared__ char smem[];
    const uint32_t sb = smem_u32(smem);
    const int tid = threadIdx.x;
    const int wid = tid >> 5, lid = tid & 31;
    const int brow = blockIdx.y * 128;
    const int bcol = blockIdx.x * 64;

    const int m0 = (wid & 1) * 64;
    const int n0 = (wid >> 1) * 32;

    float acc[2][4][4][4];   // [out][mi][n8][4]
#pragma unroll
    for (int o = 0; o < 2; ++o)
#pragma unroll
        for (int a = 0; a < 4; ++a)
#pragma unroll
            for (int b = 0; b < 4; ++b)
#pragma unroll
                for (int d = 0; d < 4; ++d) acc[o][a][b][d] = 0.f;

    const int NC = K / 64;

    auto issue = [&](int c) {
        const uint32_t st = sb + (uint32_t)(c % 3) * STG_BYTES;
        const int koff = c * 64;
        // A: [128 m][64 k] fp16, 128B rows
#pragma unroll
        for (int i = 0; i < 8; ++i) {
            int idx = tid + i * 128;
            int m = idx >> 3, cc = idx & 7;
            int g = (brow + m) * lda + koff + cc * 8;
            uint32_t off = m * 128 + (((uint32_t)(cc ^ (m & 7))) << 4);
            cpa16(st + off, Ap + g);
        }
        // B0/B1: [64 k][64 n] fp16, 128B rows
#pragma unroll
        for (int i = 0; i < 4; ++i) {
            int idx = tid + i * 128;
            int kk = idx >> 3, cc = idx & 7;
            int g = (koff + kk) * ldb + bcol + cc * 8;
            uint32_t off = kk * 128 + (((uint32_t)(cc ^ (kk & 7))) << 4);
            cpa16(st + 16384 + off, B0p + g);
            cpa16(st + 24576 + off, B1p + g);
        }
        asm volatile("cp.async.commit_group;" ::: "memory");
    };

    auto compute = [&](int c) {
        const uint32_t st = sb + (uint32_t)(c % 3) * STG_BYTES;
#pragma unroll
        for (int ks = 0; ks < 4; ++ks) {
            uint32_t af[4][4];
#pragma unroll
            for (int mi = 0; mi < 4; ++mi) {
                int row = m0 + mi * 16 + (lid & 15);
                int ch = ks * 2 + (lid >> 4);
                uint32_t off = row * 128 + (((uint32_t)(ch ^ (row & 7))) << 4);
                ldm_x4(af[mi], st + off);
            }
#pragma unroll
            for (int o = 0; o < 2; ++o) {
#pragma unroll
                for (int ni = 0; ni < 2; ++ni) {
                    int krow = ks * 16 + (lid & 7) + (lid & 8);
                    int ch = ((n0 + ni * 16) >> 3) + (lid >> 4);
                    uint32_t off = krow * 128 + (((uint32_t)(ch ^ (krow & 7))) << 4)
                                 + 16384 + (uint32_t)o * 8192;
                    uint32_t t[4];
                    ldm_x4t(t, st + off);
#pragma unroll
                    for (int mi = 0; mi < 4; ++mi) {
                        mma16816(acc[o][mi][ni * 2],     af[mi], &t[0]);
                        mma16816(acc[o][mi][ni * 2 + 1], af[mi], &t[2]);
                    }
                }
            }
        }
    };

    issue(0);
    issue(1);
    for (int c = 0; c < NC; ++c) {
        if (c + 1 < NC) asm volatile("cp.async.wait_group 1;" ::: "memory");
        else            asm volatile("cp.async.wait_group 0;" ::: "memory");
        __syncthreads();
        if (c + 2 < NC) issue(c + 2);
        compute(c);
    }

    // ---- epilogue ----
    const int r0 = lid >> 2;
    const int c0 = (lid & 3) * 2;
#pragma unroll
    for (int mi = 0; mi < 4; ++mi) {
#pragma unroll
        for (int half = 0; half < 2; ++half) {
            const int row = brow + m0 + mi * 16 + r0 + half * 8;
#pragma unroll
            for (int n8 = 0; n8 < 4; ++n8) {
                const int col = bcol + n0 + n8 * 8 + c0;
                long long lidx = ((long long)row * ldc + col) >> 1;
                float a0 = acc[0][mi][n8][half * 2];
                float a1 = acc[0][mi][n8][half * 2 + 1];
                float b0 = acc[1][mi][n8][half * 2];
                float b1 = acc[1][mi][n8][half * 2 + 1];
                if (EPI == 0) {
                    float q0 = fmaxf(a0, 0.f) * fmaxf(b0, 0.f);
                    float q1 = fmaxf(a1, 0.f) * fmaxf(b1, 0.f);
                    C0[lidx] = packh2(q0, q1);
                } else {
                    C0[lidx] = packh2(a0, a1);
                    C1[lidx] = packh2(b0, b1);
                }
            }
        }
    }
}

// ---------------------------------------------------------------------------
// Single-B GEMM (stages 4, 5). MODE 0: fp32 C0. MODE 3: scale+relu -> fp16.
// ---------------------------------------------------------------------------
template <bool TRA, int MODE>
__global__ __launch_bounds__(128, 2)
void tgemm(const uint16_t* __restrict__ Ap, const uint16_t* __restrict__ Bp,
           void* __restrict__ C0,
           int K, int lda, int ldb, int ldc,
           long long sA, long long sB, long long sC,
           const float* __restrict__ aux1, const float* __restrict__ aux2)
{
    extern __shared__ char smem[];
    const uint32_t sb = smem_u32(smem);
    const int tid = threadIdx.x;
    const int wid = tid >> 5, lid = tid & 31;
    const int z = blockIdx.z;
    const int brow = blockIdx.y * 128;
    const int bcol = blockIdx.x * 128;
    const uint16_t* A_p = Ap + z * sA;
    const uint16_t* B_p = Bp + z * sB;

    const int m0 = (wid & 1) * 64;
    const int n0 = (wid >> 1) * 64;

    float acc[4][8][4];
#pragma unroll
    for (int a = 0; a < 4; ++a)
#pragma unroll
        for (int b = 0; b < 8; ++b)
#pragma unroll
            for (int d = 0; d < 4; ++d) acc[a][b][d] = 0.f;

    const int NC = K / 64;

    auto issue = [&](int c) {
        const uint32_t st = sb + (uint32_t)(c % 3) * STG_BYTES;
        const int koff = c * 64;
        if (TRA) {
            // A: [64 k][128 m], 256B rows
#pragma unroll
            for (int i = 0; i < 8; ++i) {
                int idx = tid + i * 128;
                int kk = idx >> 4, cc = idx & 15;
                int g = (koff + kk) * lda + brow + cc * 8;
                uint32_t off = kk * 256 + (((uint32_t)(cc ^ (kk & 7))) << 4);
                cpa16(st + off, A_p + g);
            }
        } else {
            // A: [128 m][64 k], 128B rows
#pragma unroll
            for (int i = 0; i < 8; ++i) {
                int idx = tid + i * 128;
                int m = idx >> 3, cc = idx & 7;
                int g = (brow + m) * lda + koff + cc * 8;
                uint32_t off = m * 128 + (((uint32_t)(cc ^ (m & 7))) << 4);
                cpa16(st + off, A_p + g);
            }
        }
        // B: [64 k][128 n], 256B rows
#pragma unroll
        for (int i = 0; i < 8; ++i) {
            int idx = tid + i * 128;
            int kk = idx >> 4, cc = idx & 15;
            int g = (koff + kk) * ldb + bcol + cc * 8;
            uint32_t off = kk * 256 + (((uint32_t)(cc ^ (kk & 7))) << 4);
            cpa16(st + 16384 + off, B_p + g);
        }
        asm volatile("cp.async.commit_group;" ::: "memory");
    };

    auto compute = [&](int c) {
        const uint32_t st = sb + (uint32_t)(c % 3) * STG_BYTES;
#pragma unroll
        for (int ks = 0; ks < 4; ++ks) {
            uint32_t af[4][4];
#pragma unroll
            for (int mi = 0; mi < 4; ++mi) {
                if (TRA) {
                    int krow = ks * 16 + (lid & 7) + ((lid & 16) >> 1);
                    int ch = ((m0 + mi * 16) >> 3) + ((lid >> 3) & 1);
                    uint32_t off = krow * 256 + (((uint32_t)(ch ^ (krow & 7))) << 4);
                    ldm_x4t(af[mi], st + off);
                } else {
                    int row = m0 + mi * 16 + (lid & 15);
                    int ch = ks * 2 + (lid >> 4);
                    uint32_t off = row * 128 + (((uint32_t)(ch ^ (row & 7))) << 4);
                    ldm_x4(af[mi], st + off);
                }
            }
#pragma unroll
            for (int ni = 0; ni < 4; ++ni) {
                int krow = ks * 16 + (lid & 7) + (lid & 8);
                int ch = ((n0 + ni * 16) >> 3) + (lid >> 4);
                uint32_t off = krow * 256 + (((uint32_t)(ch ^ (krow & 7))) << 4) + 16384;
                uint32_t t[4];
                ldm_x4t(t, st + off);
#pragma unroll
                for (int mi = 0; mi < 4; ++mi) {
                    mma16816(acc[mi][ni * 2],     af[mi], &t[0]);
                    mma16816(acc[mi][ni * 2 + 1], af[mi], &t[2]);
                }
            }
        }
    };

    issue(0);
    issue(1);
    for (int c = 0; c < NC; ++c) {
        if (c + 1 < NC) asm volatile("cp.async.wait_group 1;" ::: "memory");
        else            asm volatile("cp.async.wait_group 0;" ::: "memory");
        __syncthreads();
        if (c + 2 < NC) issue(c + 2);
        compute(c);
    }

    // ---- epilogue ----
    const int r0 = lid >> 2;
    const int c0 = (lid & 3) * 2;
#pragma unroll
    for (int mi = 0; mi < 4; ++mi) {
#pragma unroll
        for (int half = 0; half < 2; ++half) {
            const int row = brow + m0 + mi * 16 + r0 + half * 8;
            float s1 = 1.f;
            if (MODE == 3) s1 = aux1[z * DM + row];
#pragma unroll
            for (int n8 = 0; n8 < 8; ++n8) {
                float d0 = acc[mi][n8][half * 2];
                float d1 = acc[mi][n8][half * 2 + 1];
                const int col = bcol + n0 + n8 * 8 + c0;
                if (MODE == 3) {
                    d0 = fmaxf(d0 * s1 * aux2[z * DM + col], 0.f);
                    d1 = fmaxf(d1 * s1 * aux2[z * DM + col + 1], 0.f);
                }
                long long lidx = (long long)z * sC + (long long)row * ldc + col;
                if (MODE == 0) {
                    *(float2*)((float*)C0 + lidx) = make_float2(d0, d1);
                } else {
                    ((uint32_t*)C0)[lidx >> 1] = packh2(d0, d1);
                }
            }
        }
    }
}

// ---------------------------------------------------------------------------
// Elementwise kernels
// ---------------------------------------------------------------------------
__global__ void cvt_h(const float4* __restrict__ in, uint2* __restrict__ o, int n4)
{
    int i = blockIdx.x * blockDim.x + threadIdx.x;
    if (i < n4) {
        float4 v = in[i];
        o[i] = make_uint2(packh2(v.x, v.y), packh2(v.z, v.w));
    }
}

// dual-input inverse L2 norm over sequence axis from fp16
__global__ void col_scale2_h(const uint32_t* __restrict__ X0, const uint32_t* __restrict__ X1,
                             float* __restrict__ S0, float* __restrict__ S1)
{
    __shared__ float red0[256], red1[256];
    const uint32_t* X = blockIdx.z ? X1 : X0;
    float* S = blockIdx.z ? S1 : S0;
    const int lane = threadIdx.x & 31;
    const int sl = threadIdx.x >> 5;
    const int e2 = blockIdx.x * 32 + lane;
    const int b = blockIdx.y;
    const int base = b * (NSEQ * DM / 2) + e2;
    float s0 = 0.f, s1 = 0.f;
    for (int n = sl; n < NSEQ; n += 8) {
        float2 f = unpackh2(X[base + n * (DM / 2)]);
        s0 += f.x * f.x;
        s1 += f.y * f.y;
    }
    red0[threadIdx.x] = s0;
    red1[threadIdx.x] = s1;
    __syncthreads();
    if (sl == 0) {
        float t0 = 0.f, t1 = 0.f;
#pragma unroll
        for (int i = 0; i < 8; ++i) { t0 += red0[i * 32 + lane]; t1 += red1[i * 32 + lane]; }
        S[b * DM + e2 * 2]     = 1.f / (sqrtf(t0) + EPSC);
        S[b * DM + e2 * 2 + 1] = 1.f / (sqrtf(t1) + EPSC);
    }
}

// ---------------------------------------------------------------------------
// Launch
// ---------------------------------------------------------------------------
extern "C" void kernel_launch(void* const* d_in, const int* in_sizes, int n_in,
                              void* d_out, int out_size)
{
    const float* x   = (const float*)d_in[0];
    const float* wqr = (const float*)d_in[1];
    const float* wqi = (const float*)d_in[2];
    const float* wk  = (const float*)d_in[3];
    const float* wv  = (const float*)d_in[4];
    float* out = (float*)d_out;

    uint16_t *x16, *q16, *k16, *v16, *w16, *kv16;
    float *sk, *sv;
    cudaGetSymbolAddress((void**)&x16,  g_x16);
    cudaGetSymbolAddress((void**)&q16,  g_q16);
    cudaGetSymbolAddress((void**)&k16,  g_k16);
    cudaGetSymbolAddress((void**)&v16,  g_v16);
    cudaGetSymbolAddress((void**)&w16,  g_w16);
    cudaGetSymbolAddress((void**)&kv16, g_kv16);
    cudaGetSymbolAddress((void**)&sk,   g_sk);
    cudaGetSymbolAddress((void**)&sv,   g_sv);

    cudaFuncSetAttribute(tgemm2<0>,       cudaFuncAttributeMaxDynamicSharedMemorySize, SMEM_BYTES);
    cudaFuncSetAttribute(tgemm2<1>,       cudaFuncAttributeMaxDynamicSharedMemorySize, SMEM_BYTES);
    cudaFuncSetAttribute(tgemm<false, 0>, cudaFuncAttributeMaxDynamicSharedMemorySize, SMEM_BYTES);
    cudaFuncSetAttribute(tgemm<true, 3>,  cudaFuncAttributeMaxDynamicSharedMemorySize, SMEM_BYTES);

    // Input conversions to fp16
    cvt_h<<<XELEMS / 4 / 256, 256>>>((const float4*)x, (uint2*)x16, XELEMS / 4);
    const int wn4 = 1048576 / 4;
    cvt_h<<<wn4 / 256, 256>>>((const float4*)wqr, (uint2*)w16,             wn4);
    cvt_h<<<wn4 / 256, 256>>>((const float4*)wqi, (uint2*)(w16 + 1048576), wn4);
    cvt_h<<<wn4 / 256, 256>>>((const float4*)wk,  (uint2*)(w16 + 2097152), wn4);
    cvt_h<<<wn4 / 256, 256>>>((const float4*)wv,  (uint2*)(w16 + 3145728), wn4);

    // Stage 1 fused: q (gated) and k/v in two dual-B GEMMs
    dim3 gf(DM / 64, (BSZ * NSEQ) / 128, 1);
    tgemm2<0><<<gf, 128, SMEM_BYTES>>>(x16, w16,             w16 + 1048576,
                                       (uint32_t*)q16, nullptr, DM, DM, DM, DM);
    tgemm2<1><<<gf, 128, SMEM_BYTES>>>(x16, w16 + 2097152,   w16 + 3145728,
                                       (uint32_t*)k16, (uint32_t*)v16, DM, DM, DM, DM);

    // Stage 3: inverse L2 norms (k and v in one launch)
    dim3 gs(DM / 64, BSZ, 2);
    col_scale2_h<<<gs, 256>>>((const uint32_t*)k16, (const uint32_t*)v16, sk, sv);

    // Stage 4: kv[b] = relu((K^T V) .* sk x sv) -> fp16
    dim3 g2(DM / 128, DM / 128, BSZ);
    tgemm<true, 3><<<g2, 128, SMEM_BYTES>>>(k16, v16, kv16,
                                            NSEQ, DM, DM, DM,
                                            (long long)NSEQ * DM, (long long)NSEQ * DM,
                                            (long long)DM * DM, sk, sv);

    // Stage 5: out[b] = q[b] @ kv[b] -> fp32
    dim3 g3(DM / 128, NSEQ / 128, BSZ);
    tgemm<false, 0><<<g3, 128, SMEM_BYTES>>>(q16, kv16, out,
                                             DM, DM, DM, DM,
                                             (long long)NSEQ * DM, (long long)DM * DM,
                                             (long long)NSEQ * DM, nullptr, nullptr);
}

// round 12
// speedup vs baseline: 9.1224x; 1.0004x over previous
#include <cuda_runtime.h>
#include <cuda_fp16.h>
#include <cstdint>
#include <math.h>

#define BSZ   8
#define NSEQ  4096
#define DM    1024
#define EPSC  1e-5f

// ---------------------------------------------------------------------------
// Scratch (device globals). fp16 stored as uint16_t.
// ---------------------------------------------------------------------------
#define XELEMS (8u * 4096u * 1024u)
__device__ uint16_t g_x16[XELEMS];                 // x fp16
__device__ uint16_t g_q16[XELEMS];                 // q fp16 (gated)
__device__ uint16_t g_k16[XELEMS];                 // k fp16
__device__ uint16_t g_v16[XELEMS];                 // v fp16
__device__ uint16_t g_w16[4u * 1048576u];          // 4 weights fp16
__device__ uint16_t g_kv16[8u * 1048576u];         // kv fp16
__device__ float    g_sk[8u * 1024u], g_sv[8u * 1024u];

// ---------------------------------------------------------------------------
// Helpers
// ---------------------------------------------------------------------------
__device__ __forceinline__ uint32_t smem_u32(const void* p) {
    uint32_t a;
    asm("{ .reg .u64 t; cvta.to.shared.u64 t, %1; cvt.u32.u64 %0, t; }" : "=r"(a) : "l"(p));
    return a;
}
__device__ __forceinline__ uint32_t packh2(float x, float y) {
    __half2 h = __floats2half2_rn(x, y);
    return *reinterpret_cast<uint32_t*>(&h);
}
__device__ __forceinline__ float2 unpackh2(uint32_t u) {
    __half2 h = *reinterpret_cast<__half2*>(&u);
    return __half22float2(h);
}
__device__ __forceinline__ void ldm_x4(uint32_t* d, uint32_t a) {
    asm volatile("ldmatrix.sync.aligned.m8n8.x4.shared.b16 {%0,%1,%2,%3}, [%4];"
                 : "=r"(d[0]), "=r"(d[1]), "=r"(d[2]), "=r"(d[3]) : "r"(a));
}
__device__ __forceinline__ void ldm_x4t(uint32_t* d, uint32_t a) {
    asm volatile("ldmatrix.sync.aligned.m8n8.x4.trans.shared.b16 {%0,%1,%2,%3}, [%4];"
                 : "=r"(d[0]), "=r"(d[1]), "=r"(d[2]), "=r"(d[3]) : "r"(a));
}
__device__ __forceinline__ void mma16816(float* d, const uint32_t* a, const uint32_t* b) {
    asm volatile("mma.sync.aligned.m16n8k16.row.col.f32.f16.f16.f32 "
                 "{%0,%1,%2,%3}, {%4,%5,%6,%7}, {%8,%9}, {%0,%1,%2,%3};"
                 : "+f"(d[0]), "+f"(d[1]), "+f"(d[2]), "+f"(d[3])
                 : "r"(a[0]), "r"(a[1]), "r"(a[2]), "r"(a[3]), "r"(b[0]), "r"(b[1]));
}
__device__ __forceinline__ void cpa16(uint32_t s, const void* g) {
    asm volatile("cp.async.cg.shared.global [%0], [%1], 16;" :: "r"(s), "l"(g));
}

// ===========================================================================
// Common config: BM=BN=128, BK=64, 128 threads, 4 warps, warp tile 64x64
// (single-B) / 64x(32+32) (dual-B). 3-stage cp.async, one sync per BK=64.
// A smem (direct): [128 m][64 k], 128B rows, chunk^(m&7) swizzle  (16 KB)
// A smem (TRA)   : [64 k][128 m], 256B rows, chunk^(k&7) swizzle  (16 KB)
// B smem         : [64 k][128 n], 256B rows, chunk^(k&7) swizzle  (16 KB)
// B_o smem (dual): [64 k][64 n],  128B rows, chunk^(k&7) swizzle  (8 KB x2)
// ===========================================================================
#define STG_BYTES 32768u
#define SMEM_BYTES 98304

// ---------------------------------------------------------------------------
// Fused dual-B GEMM (stage 1). EPI 0: C0 = fp16(relu(a)*relu(b)).
// EPI 1: C0 = fp16(a), C1 = fp16(b).
// ---------------------------------------------------------------------------
template <int EPI>
__global__ __launch_bounds__(128, 2)
void tgemm2(const uint16_t* __restrict__ Ap, const uint16_t* __restrict__ B0p,
            const uint16_t* __restrict__ B1p,
            uint32_t* __restrict__ C0, uint32_t* __restrict__ C1,
            int K, int lda, int ldb, int ldc)
{
    extern __shared__ char smem[];
    const uint32_t sb = smem_u32(smem);
    const int tid = threadIdx.x;
    const int wid = tid >> 5, lid = tid & 31;
    const int brow = blockIdx.y * 128;
    const int bcol = blockIdx.x * 64;

    const int m0 = (wid & 1) * 64;
    const int n0 = (wid >> 1) * 32;

    float acc[2][4][4][4];   // [out][mi][n8][4]
#pragma unroll
    for (int o = 0; o < 2; ++o)
#pragma unroll
        for (int a = 0; a < 4; ++a)
#pragma unroll
            for (int b = 0; b < 4; ++b)
#pragma unroll
                for (int d = 0; d < 4; ++d) acc[o][a][b][d] = 0.f;

    const int NC = K / 64;

    auto issue = [&](int c) {
        const uint32_t st = sb + (uint32_t)(c % 3) * STG_BYTES;
        const int koff = c * 64;
        // A: [128 m][64 k] fp16, 128B rows
#pragma unroll
        for (int i = 0; i < 8; ++i) {
            int idx = tid + i * 128;
            int m = idx >> 3, cc = idx & 7;
            int g = (brow + m) * lda + koff + cc * 8;
            uint32_t off = m * 128 + (((uint32_t)(cc ^ (m & 7))) << 4);
            cpa16(st + off, Ap + g);
        }
        // B0/B1: [64 k][64 n] fp16, 128B rows
#pragma unroll
        for (int i = 0; i < 4; ++i) {
            int idx = tid + i * 128;
            int kk = idx >> 3, cc = idx & 7;
            int g = (koff + kk) * ldb + bcol + cc * 8;
            uint32_t off = kk * 128 + (((uint32_t)(cc ^ (kk & 7))) << 4);
            cpa16(st + 16384 + off, B0p + g);
            cpa16(st + 24576 + off, B1p + g);
        }
        asm volatile("cp.async.commit_group;" ::: "memory");
    };

    auto compute = [&](int c) {
        const uint32_t st = sb + (uint32_t)(c % 3) * STG_BYTES;
#pragma unroll
        for (int ks = 0; ks < 4; ++ks) {
            uint32_t af[4][4];
#pragma unroll
            for (int mi = 0; mi < 4; ++mi) {
                int row = m0 + mi * 16 + (lid & 15);
                int ch = ks * 2 + (lid >> 4);
                uint32_t off = row * 128 + (((uint32_t)(ch ^ (row & 7))) << 4);
                ldm_x4(af[mi], st + off);
            }
#pragma unroll
            for (int o = 0; o < 2; ++o) {
#pragma unroll
                for (int ni = 0; ni < 2; ++ni) {
                    int krow = ks * 16 + (lid & 7) + (lid & 8);
                    int ch = ((n0 + ni * 16) >> 3) + (lid >> 4);
                    uint32_t off = krow * 128 + (((uint32_t)(ch ^ (krow & 7))) << 4)
                                 + 16384 + (uint32_t)o * 8192;
                    uint32_t t[4];
                    ldm_x4t(t, st + off);
#pragma unroll
                    for (int mi = 0; mi < 4; ++mi) {
                        mma16816(acc[o][mi][ni * 2],     af[mi], &t[0]);
                        mma16816(acc[o][mi][ni * 2 + 1], af[mi], &t[2]);
                    }
                }
            }
        }
    };

    issue(0);
    issue(1);
    for (int c = 0; c < NC; ++c) {
        if (c + 1 < NC) asm volatile("cp.async.wait_group 1;" ::: "memory");
        else            asm volatile("cp.async.wait_group 0;" ::: "memory");
        __syncthreads();
        if (c + 2 < NC) issue(c + 2);
        compute(c);
    }

    // ---- epilogue ----
    const int r0 = lid >> 2;
    const int c0 = (lid & 3) * 2;
#pragma unroll
    for (int mi = 0; mi < 4; ++mi) {
#pragma unroll
        for (int half = 0; half < 2; ++half) {
            const int row = brow + m0 + mi * 16 + r0 + half * 8;
#pragma unroll
            for (int n8 = 0; n8 < 4; ++n8) {
                const int col = bcol + n0 + n8 * 8 + c0;
                long long lidx = ((long long)row * ldc + col) >> 1;
                float a0 = acc[0][mi][n8][half * 2];
                float a1 = acc[0][mi][n8][half * 2 + 1];
                float b0 = acc[1][mi][n8][half * 2];
                float b1 = acc[1][mi][n8][half * 2 + 1];
                if (EPI == 0) {
                    float q0 = fmaxf(a0, 0.f) * fmaxf(b0, 0.f);
                    float q1 = fmaxf(a1, 0.f) * fmaxf(b1, 0.f);
                    C0[lidx] = packh2(q0, q1);
                } else {
                    C0[lidx] = packh2(a0, a1);
                    C1[lidx] = packh2(b0, b1);
                }
            }
        }
    }
}

// ---------------------------------------------------------------------------
// Single-B GEMM (stages 4, 5). MODE 0: fp32 C0. MODE 3: scale+relu -> fp16.
// ---------------------------------------------------------------------------
template <bool TRA, int MODE>
__global__ __launch_bounds__(128, 2)
void tgemm(const uint16_t* __restrict__ Ap, const uint16_t* __restrict__ Bp,
           void* __restrict__ C0,
           int K, int lda, int ldb, int ldc,
           long long sA, long long sB, long long sC,
           const float* __restrict__ aux1, const float* __restrict__ aux2)
{
    extern __shared__ char smem[];
    const uint32_t sb = smem_u32(smem);
    const int tid = threadIdx.x;
    const int wid = tid >> 5, lid = tid & 31;
    const int z = blockIdx.z;
    const int brow = blockIdx.y * 128;
    const int bcol = blockIdx.x * 128;
    const uint16_t* A_p = Ap + z * sA;
    const uint16_t* B_p = Bp + z * sB;

    const int m0 = (wid & 1) * 64;
    const int n0 = (wid >> 1) * 64;

    float acc[4][8][4];
#pragma unroll
    for (int a = 0; a < 4; ++a)
#pragma unroll
        for (int b = 0; b < 8; ++b)
#pragma unroll
            for (int d = 0; d < 4; ++d) acc[a][b][d] = 0.f;

    const int NC = K / 64;

    auto issue = [&](int c) {
        const uint32_t st = sb + (uint32_t)(c % 3) * STG_BYTES;
        const int koff = c * 64;
        if (TRA) {
            // A: [64 k][128 m], 256B rows
#pragma unroll
            for (int i = 0; i < 8; ++i) {
                int idx = tid + i * 128;
                int kk = idx >> 4, cc = idx & 15;
                int g = (koff + kk) * lda + brow + cc * 8;
                uint32_t off = kk * 256 + (((uint32_t)(cc ^ (kk & 7))) << 4);
                cpa16(st + off, A_p + g);
            }
        } else {
            // A: [128 m][64 k], 128B rows
#pragma unroll
            for (int i = 0; i < 8; ++i) {
                int idx = tid + i * 128;
                int m = idx >> 3, cc = idx & 7;
                int g = (brow + m) * lda + koff + cc * 8;
                uint32_t off = m * 128 + (((uint32_t)(cc ^ (m & 7))) << 4);
                cpa16(st + off, A_p + g);
            }
        }
        // B: [64 k][128 n], 256B rows
#pragma unroll
        for (int i = 0; i < 8; ++i) {
            int idx = tid + i * 128;
            int kk = idx >> 4, cc = idx & 15;
            int g = (koff + kk) * ldb + bcol + cc * 8;
            uint32_t off = kk * 256 + (((uint32_t)(cc ^ (kk & 7))) << 4);
            cpa16(st + 16384 + off, B_p + g);
        }
        asm volatile("cp.async.commit_group;" ::: "memory");
    };

    auto compute = [&](int c) {
        const uint32_t st = sb + (uint32_t)(c % 3) * STG_BYTES;
#pragma unroll
        for (int ks = 0; ks < 4; ++ks) {
            uint32_t af[4][4];
#pragma unroll
            for (int mi = 0; mi < 4; ++mi) {
                if (TRA) {
                    int krow = ks * 16 + (lid & 7) + ((lid & 16) >> 1);
                    int ch = ((m0 + mi * 16) >> 3) + ((lid >> 3) & 1);
                    uint32_t off = krow * 256 + (((uint32_t)(ch ^ (krow & 7))) << 4);
                    ldm_x4t(af[mi], st + off);
                } else {
                    int row = m0 + mi * 16 + (lid & 15);
                    int ch = ks * 2 + (lid >> 4);
                    uint32_t off = row * 128 + (((uint32_t)(ch ^ (row & 7))) << 4);
                    ldm_x4(af[mi], st + off);
                }
            }
#pragma unroll
            for (int ni = 0; ni < 4; ++ni) {
                int krow = ks * 16 + (lid & 7) + (lid & 8);
                int ch = ((n0 + ni * 16) >> 3) + (lid >> 4);
                uint32_t off = krow * 256 + (((uint32_t)(ch ^ (krow & 7))) << 4) + 16384;
                uint32_t t[4];
                ldm_x4t(t, st + off);
#pragma unroll
                for (int mi = 0; mi < 4; ++mi) {
                    mma16816(acc[mi][ni * 2],     af[mi], &t[0]);
                    mma16816(acc[mi][ni * 2 + 1], af[mi], &t[2]);
                }
            }
        }
    };

    issue(0);
    issue(1);
    for (int c = 0; c < NC; ++c) {
        if (c + 1 < NC) asm volatile("cp.async.wait_group 1;" ::: "memory");
        else            asm volatile("cp.async.wait_group 0;" ::: "memory");
        __syncthreads();
        if (c + 2 < NC) issue(c + 2);
        compute(c);
    }

    // ---- epilogue ----
    const int r0 = lid >> 2;
    const int c0 = (lid & 3) * 2;
#pragma unroll
    for (int mi = 0; mi < 4; ++mi) {
#pragma unroll
        for (int half = 0; half < 2; ++half) {
            const int row = brow + m0 + mi * 16 + r0 + half * 8;
            float s1 = 1.f;
            if (MODE == 3) s1 = aux1[z * DM + row];
#pragma unroll
            for (int n8 = 0; n8 < 8; ++n8) {
                float d0 = acc[mi][n8][half * 2];
                float d1 = acc[mi][n8][half * 2 + 1];
                const int col = bcol + n0 + n8 * 8 + c0;
                if (MODE == 3) {
                    d0 = fmaxf(d0 * s1 * aux2[z * DM + col], 0.f);
                    d1 = fmaxf(d1 * s1 * aux2[z * DM + col + 1], 0.f);
                }
                long long lidx = (long long)z * sC + (long long)row * ldc + col;
                if (MODE == 0) {
                    *(float2*)((float*)C0 + lidx) = make_float2(d0, d1);
                } else {
                    ((uint32_t*)C0)[lidx >> 1] = packh2(d0, d1);
                }
            }
        }
    }
}

// ---------------------------------------------------------------------------
// Elementwise kernels
// ---------------------------------------------------------------------------
__global__ void cvt_h(const float4* __restrict__ in, uint2* __restrict__ o, int n4)
{
    int i = blockIdx.x * blockDim.x + threadIdx.x;
    if (i < n4) {
        float4 v = in[i];
        o[i] = make_uint2(packh2(v.x, v.y), packh2(v.z, v.w));
    }
}

// dual-input inverse L2 norm over sequence axis from fp16
__global__ void col_scale2_h(const uint32_t* __restrict__ X0, const uint32_t* __restrict__ X1,
                             float* __restrict__ S0, float* __restrict__ S1)
{
    __shared__ float red0[256], red1[256];
    const uint32_t* X = blockIdx.z ? X1 : X0;
    float* S = blockIdx.z ? S1 : S0;
    const int lane = threadIdx.x & 31;
    const int sl = threadIdx.x >> 5;
    const int e2 = blockIdx.x * 32 + lane;
    const int b = blockIdx.y;
    const int base = b * (NSEQ * DM / 2) + e2;
    float s0 = 0.f, s1 = 0.f;
    for (int n = sl; n < NSEQ; n += 8) {
        float2 f = unpackh2(X[base + n * (DM / 2)]);
        s0 += f.x * f.x;
        s1 += f.y * f.y;
    }
    red0[threadIdx.x] = s0;
    red1[threadIdx.x] = s1;
    __syncthreads();
    if (sl == 0) {
        float t0 = 0.f, t1 = 0.f;
#pragma unroll
        for (int i = 0; i < 8; ++i) { t0 += red0[i * 32 + lane]; t1 += red1[i * 32 + lane]; }
        S[b * DM + e2 * 2]     = 1.f / (sqrtf(t0) + EPSC);
        S[b * DM + e2 * 2 + 1] = 1.f / (sqrtf(t1) + EPSC);
    }
}

// ---------------------------------------------------------------------------
// Launch
// ---------------------------------------------------------------------------
extern "C" void kernel_launch(void* const* d_in, const int* in_sizes, int n_in,
                              void* d_out, int out_size)
{
    const float* x   = (const float*)d_in[0];
    const float* wqr = (const float*)d_in[1];
    const float* wqi = (const float*)d_in[2];
    const float* wk  = (const float*)d_in[3];
    const float* wv  = (const float*)d_in[4];
    float* out = (float*)d_out;

    uint16_t *x16, *q16, *k16, *v16, *w16, *kv16;
    float *sk, *sv;
    cudaGetSymbolAddress((void**)&x16,  g_x16);
    cudaGetSymbolAddress((void**)&q16,  g_q16);
    cudaGetSymbolAddress((void**)&k16,  g_k16);
    cudaGetSymbolAddress((void**)&v16,  g_v16);
    cudaGetSymbolAddress((void**)&w16,  g_w16);
    cudaGetSymbolAddress((void**)&kv16, g_kv16);
    cudaGetSymbolAddress((void**)&sk,   g_sk);
    cudaGetSymbolAddress((void**)&sv,   g_sv);

    cudaFuncSetAttribute(tgemm2<0>,       cudaFuncAttributeMaxDynamicSharedMemorySize, SMEM_BYTES);
    cudaFuncSetAttribute(tgemm2<1>,       cudaFuncAttributeMaxDynamicSharedMemorySize, SMEM_BYTES);
    cudaFuncSetAttribute(tgemm<false, 0>, cudaFuncAttributeMaxDynamicSharedMemorySize, SMEM_BYTES);
    cudaFuncSetAttribute(tgemm<true, 3>,  cudaFuncAttributeMaxDynamicSharedMemorySize, SMEM_BYTES);

    // Input conversions to fp16
    cvt_h<<<XELEMS / 4 / 256, 256>>>((const float4*)x, (uint2*)x16, XELEMS / 4);
    const int wn4 = 1048576 / 4;
    cvt_h<<<wn4 / 256, 256>>>((const float4*)wqr, (uint2*)w16,             wn4);
    cvt_h<<<wn4 / 256, 256>>>((const float4*)wqi, (uint2*)(w16 + 1048576), wn4);
    cvt_h<<<wn4 / 256, 256>>>((const float4*)wk,  (uint2*)(w16 + 2097152), wn4);
    cvt_h<<<wn4 / 256, 256>>>((const float4*)wv,  (uint2*)(w16 + 3145728), wn4);

    // Stage 1 fused: q (gated) and k/v in two dual-B GEMMs
    dim3 gf(DM / 64, (BSZ * NSEQ) / 128, 1);
    tgemm2<0><<<gf, 128, SMEM_BYTES>>>(x16, w16,             w16 + 1048576,
                                       (uint32_t*)q16, nullptr, DM, DM, DM, DM);
    tgemm2<1><<<gf, 128, SMEM_BYTES>>>(x16, w16 + 2097152,   w16 + 3145728,
                                       (uint32_t*)k16, (uint32_t*)v16, DM, DM, DM, DM);

    // Stage 3: inverse L2 norms (k and v in one launch)
    dim3 gs(DM / 64, BSZ, 2);
    col_scale2_h<<<gs, 256>>>((const uint32_t*)k16, (const uint32_t*)v16, sk, sv);

    // Stage 4: kv[b] = relu((K^T V) .* sk x sv) -> fp16
    dim3 g2(DM / 128, DM / 128, BSZ);
    tgemm<true, 3><<<g2, 128, SMEM_BYTES>>>(k16, v16, kv16,
                                            NSEQ, DM, DM, DM,
                                            (long long)NSEQ * DM, (long long)NSEQ * DM,
                                            (long long)DM * DM, sk, sv);

    // Stage 5: out[b] = q[b] @ kv[b] -> fp32
    dim3 g3(DM / 128, NSEQ / 128, BSZ);
    tgemm<false, 0><<<g3, 128, SMEM_BYTES>>>(q16, kv16, out,
                                             DM, DM, DM, DM,
                                             (long long)NSEQ * DM, (long long)DM * DM,
                                             (long long)NSEQ * DM, nullptr, nullptr);
}